// round 12
// baseline (speedup 1.0000x reference)
#include <cuda_runtime.h>
#include <cstdint>

#define Bv 4
#define Sv 2048
#define Dv 1024
#define Hv 16
#define DHv 64
#define Mv (Bv*Sv)          // 8192

// Scratch (tf32 bit patterns everywhere)
__device__ uint32_t g_qin[Mv*Dv];
__device__ uint32_t g_kin[Mv*Dv];
__device__ uint32_t g_vin[Mv*Dv];
__device__ uint32_t g_wq[Dv*Dv];
__device__ uint32_t g_wk[Dv*Dv];
__device__ uint32_t g_wv[Dv*Dv];
__device__ uint32_t g_wo[Dv*Dv];
__device__ uint32_t g_q[Mv*Dv];    // [b,h,s,dh]
__device__ uint32_t g_k[Mv*Dv];
__device__ uint32_t g_v[Mv*Dv];
__device__ uint32_t g_ctx[Mv*Dv];  // [b,s,h,dh]

__device__ __forceinline__ uint32_t f2tf32(float x) {
    uint32_t r;
    asm("cvt.rna.tf32.f32 %0, %1;" : "=r"(r) : "f"(x));
    return r;
}

__device__ __forceinline__ void mma_tf32(float c[4], const uint32_t a[4], const uint32_t b[2]) {
    asm volatile(
        "mma.sync.aligned.m16n8k8.row.col.f32.tf32.tf32.f32 "
        "{%0,%1,%2,%3}, {%4,%5,%6,%7}, {%8,%9}, {%0,%1,%2,%3};\n"
        : "+f"(c[0]), "+f"(c[1]), "+f"(c[2]), "+f"(c[3])
        : "r"(a[0]), "r"(a[1]), "r"(a[2]), "r"(a[3]), "r"(b[0]), "r"(b[1]));
}

__device__ __forceinline__ void cpa16(uint32_t saddr, const void* gptr) {
    asm volatile("cp.async.cg.shared.global [%0], [%1], 16;" :: "r"(saddr), "l"(gptr));
}
__device__ __forceinline__ void cpa_commit() {
    asm volatile("cp.async.commit_group;" ::: "memory");
}

// ---------------- conversions ----------------

__global__ __launch_bounds__(256) void cvt3_kernel(
    const float4* __restrict__ a, const float4* __restrict__ b, const float4* __restrict__ c,
    uint4* __restrict__ oa, uint4* __restrict__ ob, uint4* __restrict__ oc, int n4)
{
    const float4* in  = (blockIdx.y == 0) ? a  : (blockIdx.y == 1) ? b  : c;
    uint4*        out = (blockIdx.y == 0) ? oa : (blockIdx.y == 1) ? ob : oc;
    int i = blockIdx.x * blockDim.x + threadIdx.x;
    int stride = gridDim.x * blockDim.x;
    for (; i < n4; i += stride) {
        float4 v = in[i];
        out[i] = make_uint4(f2tf32(v.x), f2tf32(v.y), f2tf32(v.z), f2tf32(v.w));
    }
}

__global__ __launch_bounds__(256) void cvt4_kernel(
    const float4* __restrict__ a, const float4* __restrict__ b,
    const float4* __restrict__ c, const float4* __restrict__ d,
    uint4* __restrict__ oa, uint4* __restrict__ ob,
    uint4* __restrict__ oc, uint4* __restrict__ od, int n4)
{
    const float4* in  = (blockIdx.y == 0) ? a  : (blockIdx.y == 1) ? b  : (blockIdx.y == 2) ? c  : d;
    uint4*        out = (blockIdx.y == 0) ? oa : (blockIdx.y == 1) ? ob : (blockIdx.y == 2) ? oc : od;
    int i = blockIdx.x * blockDim.x + threadIdx.x;
    int stride = gridDim.x * blockDim.x;
    for (; i < n4; i += stride) {
        float4 v = in[i];
        out[i] = make_uint4(f2tf32(v.x), f2tf32(v.y), f2tf32(v.z), f2tf32(v.w));
    }
}

// ---------------- GEMM: block 128(M) x 256(N), warp 64x64, 3-stage cp.async ----------------

#define AST (128 * 36)          // A stage words
#define BST (256 * 36)          // B stage words
#define GST (AST + BST)         // words per stage
#define GEMM_SMEM_WORDS (3 * GST)

__device__ __forceinline__ void gemm_body(
    const uint32_t* __restrict__ A, const uint32_t* __restrict__ W,
    const float* __restrict__ bias, void* __restrict__ Cout,
    int bm, int bn, int scatter, uint32_t* smg)
{
    const uint32_t smb = (uint32_t)__cvta_generic_to_shared(smg);

    const int tid  = threadIdx.x;
    const int warp = tid >> 5;
    const int lane = tid & 31;
    const int wm   = (warp >> 2) * 64;   // 2 warps along M
    const int wn   = (warp & 3) * 64;    // 4 warps along N
    const int g    = lane >> 2;
    const int tig  = lane & 3;

    float acc[4][8][4];
    #pragma unroll
    for (int i = 0; i < 4; i++)
        #pragma unroll
        for (int j = 0; j < 8; j++)
            #pragma unroll
            for (int t = 0; t < 4; t++) acc[i][j][t] = 0.f;

    // stage slab kt: A 128x32 (4 chunks/thread), B 256x32 (8 chunks/thread)
    auto issue = [&](int st, int kt) {
        uint32_t abase = smb + (uint32_t)(st * GST) * 4;
        uint32_t bbase = abase + (uint32_t)AST * 4;
        #pragma unroll
        for (int u = 0; u < 4; u++) {
            int id = tid + u * 256;
            int r = id >> 3, c = (id & 7) << 2;
            cpa16(abase + (uint32_t)(r * 36 + c) * 4,
                  &A[(size_t)(bm + r) * Dv + kt + c]);
        }
        #pragma unroll
        for (int u = 0; u < 8; u++) {
            int id = tid + u * 256;
            int r = id >> 3, c = (id & 7) << 2;
            cpa16(bbase + (uint32_t)(r * 36 + c) * 4,
                  &W[(size_t)(bn + r) * Dv + kt + c]);
        }
        cpa_commit();
    };

    issue(0, 0);
    issue(1, 32);

    for (int t = 0; t < 32; t++) {
        if (t == 31) asm volatile("cp.async.wait_group 0;" ::: "memory");
        else         asm volatile("cp.async.wait_group 1;" ::: "memory");
        __syncthreads();
        if (t + 2 < 32) issue((t + 2) % 3, (t + 2) * 32);

        const uint32_t* Ab = smg + (t % 3) * GST;
        const uint32_t* Bb = Ab + AST;

        #pragma unroll
        for (int k0 = 0; k0 < 32; k0 += 8) {
            uint32_t af[4][4], bf[8][2];
            #pragma unroll
            for (int i = 0; i < 4; i++) {
                int r0 = wm + i * 16;
                af[i][0] = Ab[(r0 + g    ) * 36 + k0 + tig    ];
                af[i][1] = Ab[(r0 + g + 8) * 36 + k0 + tig    ];
                af[i][2] = Ab[(r0 + g    ) * 36 + k0 + tig + 4];
                af[i][3] = Ab[(r0 + g + 8) * 36 + k0 + tig + 4];
            }
            #pragma unroll
            for (int j = 0; j < 8; j++) {
                int c0 = wn + j * 8;
                bf[j][0] = Bb[(c0 + g) * 36 + k0 + tig    ];
                bf[j][1] = Bb[(c0 + g) * 36 + k0 + tig + 4];
            }
            #pragma unroll
            for (int i = 0; i < 4; i++)
                #pragma unroll
                for (int j = 0; j < 8; j++)
                    mma_tf32(acc[i][j], af[i], bf[j]);
        }
        __syncthreads();
    }

    #pragma unroll
    for (int i = 0; i < 4; i++) {
        #pragma unroll
        for (int j = 0; j < 8; j++) {
            int r0 = bm + wm + i * 16 + g;
            int r1 = r0 + 8;
            int c0 = bn + wn + j * 8 + 2 * tig;
            float b0 = bias[c0], b1 = bias[c0 + 1];
            float v00 = acc[i][j][0] + b0, v01 = acc[i][j][1] + b1;
            float v10 = acc[i][j][2] + b0, v11 = acc[i][j][3] + b1;
            if (scatter) {
                uint32_t* C = (uint32_t*)Cout;
                int b_0 = r0 >> 11, s_0 = r0 & 2047;
                int b_1 = r1 >> 11, s_1 = r1 & 2047;
                int h = c0 >> 6, dh = c0 & 63;
                size_t i0 = ((((size_t)b_0 * Hv + h) * Sv) + s_0) * DHv + dh;
                size_t i1 = ((((size_t)b_1 * Hv + h) * Sv) + s_1) * DHv + dh;
                C[i0] = f2tf32(v00); C[i0 + 1] = f2tf32(v01);
                C[i1] = f2tf32(v10); C[i1 + 1] = f2tf32(v11);
            } else {
                float* C = (float*)Cout;
                C[(size_t)r0 * Dv + c0] = v00; C[(size_t)r0 * Dv + c0 + 1] = v01;
                C[(size_t)r1 * Dv + c0] = v10; C[(size_t)r1 * Dv + c0 + 1] = v11;
            }
        }
    }
}

__global__ __launch_bounds__(256, 1) void proj_qkv(
    const uint32_t* __restrict__ Aq, const uint32_t* __restrict__ Ak, const uint32_t* __restrict__ Av,
    const uint32_t* __restrict__ Wq, const uint32_t* __restrict__ Wk, const uint32_t* __restrict__ Wv,
    const float* __restrict__ bq, const float* __restrict__ bk, const float* __restrict__ bv,
    uint32_t* __restrict__ Oq, uint32_t* __restrict__ Ok, uint32_t* __restrict__ Ov)
{
    extern __shared__ uint32_t smg[];
    const uint32_t* A = (blockIdx.z == 0) ? Aq : (blockIdx.z == 1) ? Ak : Av;
    const uint32_t* W = (blockIdx.z == 0) ? Wq : (blockIdx.z == 1) ? Wk : Wv;
    const float*    bb = (blockIdx.z == 0) ? bq : (blockIdx.z == 1) ? bk : bv;
    uint32_t*       O = (blockIdx.z == 0) ? Oq : (blockIdx.z == 1) ? Ok : Ov;
    gemm_body(A, W, bb, O, blockIdx.y * 128, blockIdx.x * 256, 1, smg);
}

__global__ __launch_bounds__(256, 1) void gemm_out(
    const uint32_t* __restrict__ A, const uint32_t* __restrict__ W,
    const float* __restrict__ bias, float* __restrict__ C)
{
    extern __shared__ uint32_t smg[];
    gemm_body(A, W, bias, C, blockIdx.y * 128, blockIdx.x * 256, 0, smg);
}

// ---------------- flash attention (exact R7-proven version) ----------------
// Br=256 (8 warps x 32 q-rows, 2 m-blocks), Bc=64.
__global__ __launch_bounds__(256) void flash_attn(const int* __restrict__ mask)
{
    extern __shared__ uint32_t smf[];
    const int QOFF = 0;
    const int KOFF = 256 * 68;
    const int VOFF = KOFF + 2 * 64 * 68;
    const int TSZ  = 64 * 68;
    const uint32_t smb = (uint32_t)__cvta_generic_to_shared(smf);

    const int qt  = blockIdx.x;
    const int bh  = blockIdx.y;
    const int b   = bh >> 4;
    const int h   = bh & 15;
    const uint32_t* Qg = g_q + (size_t)bh * Sv * DHv + (size_t)qt * 256 * DHv;
    const uint32_t* Kg = g_k + (size_t)bh * Sv * DHv;
    const uint32_t* Vg = g_v + (size_t)bh * Sv * DHv;
    const int* mrow = mask + b * Sv;

    const int tid  = threadIdx.x;
    const int warp = tid >> 5;
    const int lane = tid & 31;
    const int g    = lane >> 2;
    const int tig  = lane & 3;
    const int rw   = warp * 32;

    #pragma unroll
    for (int i = tid; i < 256 * 16; i += 256) {
        int r = i >> 4, c = (i & 15) << 2;
        *(uint4*)&smf[QOFF + r * 68 + c] = *(const uint4*)&Qg[r * 64 + c];
    }

    auto issue_kv = [&](int st, int jt) {
        #pragma unroll
        for (int u = 0; u < 4; u++) {
            int id = tid + u * 256;
            int r = id >> 4, c = (id & 15) << 2;
            cpa16(smb + (uint32_t)(KOFF + st * TSZ + r * 68 + c) * 4,
                  &Kg[(jt * 64 + r) * 64 + c]);
            cpa16(smb + (uint32_t)(VOFF + st * TSZ + r * 68 + c) * 4,
                  &Vg[(jt * 64 + r) * 64 + c]);
        }
        cpa_commit();
    };

    float m_[4], l_[4];
    #pragma unroll
    for (int i = 0; i < 4; i++) { m_[i] = -1e30f; l_[i] = 0.f; }

    float o[2][8][4];
    #pragma unroll
    for (int mb = 0; mb < 2; mb++)
        #pragma unroll
        for (int n = 0; n < 8; n++)
            #pragma unroll
            for (int q = 0; q < 4; q++) o[mb][n][q] = 0.f;

    const float scale = 0.03125f;
    const int srcA = (lane & 28) | (tig >> 1);
    const int srcB = srcA + 2;
    const bool podd = (tig & 1) != 0;

    issue_kv(0, 0);

    for (int jt = 0; jt < Sv / 64; jt++) {
        asm volatile("cp.async.wait_group 0;" ::: "memory");
        __syncthreads();
        if (jt + 1 < Sv / 64) issue_kv((jt + 1) & 1, jt + 1);

        const uint32_t* Ks = smf + KOFF + (jt & 1) * TSZ;
        const uint32_t* Vs = smf + VOFF + (jt & 1) * TSZ;

        float s[2][8][4];
        #pragma unroll
        for (int mb = 0; mb < 2; mb++)
            #pragma unroll
            for (int n = 0; n < 8; n++)
                #pragma unroll
                for (int q = 0; q < 4; q++) s[mb][n][q] = 0.f;

        #pragma unroll
        for (int k0 = 0; k0 < 64; k0 += 8) {
            uint32_t aq[2][4];
            #pragma unroll
            for (int mb = 0; mb < 2; mb++) {
                int r0 = rw + mb * 16;
                aq[mb][0] = smf[QOFF + (r0 + g    ) * 68 + k0 + tig    ];
                aq[mb][1] = smf[QOFF + (r0 + g + 8) * 68 + k0 + tig    ];
                aq[mb][2] = smf[QOFF + (r0 + g    ) * 68 + k0 + tig + 4];
                aq[mb][3] = smf[QOFF + (r0 + g + 8) * 68 + k0 + tig + 4];
            }
            #pragma unroll
            for (int n = 0; n < 8; n++) {
                uint32_t bf[2];
                bf[0] = Ks[(n * 8 + g) * 68 + k0 + tig    ];
                bf[1] = Ks[(n * 8 + g) * 68 + k0 + tig + 4];
                mma_tf32(s[0][n], aq[0], bf);
                mma_tf32(s[1][n], aq[1], bf);
            }
        }

        float rmax[4];
        #pragma unroll
        for (int i = 0; i < 4; i++) rmax[i] = -1e30f;
        #pragma unroll
        for (int n = 0; n < 8; n++) {
            int c0 = jt * 64 + n * 8 + 2 * tig;
            float msk0 = mrow[c0]     ? 0.f : -1e30f;
            float msk1 = mrow[c0 + 1] ? 0.f : -1e30f;
            #pragma unroll
            for (int mb = 0; mb < 2; mb++) {
                s[mb][n][0] = s[mb][n][0] * scale + msk0;
                s[mb][n][1] = s[mb][n][1] * scale + msk1;
                s[mb][n][2] = s[mb][n][2] * scale + msk0;
                s[mb][n][3] = s[mb][n][3] * scale + msk1;
                rmax[mb*2  ] = fmaxf(rmax[mb*2  ], fmaxf(s[mb][n][0], s[mb][n][1]));
                rmax[mb*2+1] = fmaxf(rmax[mb*2+1], fmaxf(s[mb][n][2], s[mb][n][3]));
            }
        }
        #pragma unroll
        for (int i = 0; i < 4; i++) {
            rmax[i] = fmaxf(rmax[i], __shfl_xor_sync(0xffffffffu, rmax[i], 1));
            rmax[i] = fmaxf(rmax[i], __shfl_xor_sync(0xffffffffu, rmax[i], 2));
        }

        float al[4], mn[4];
        #pragma unroll
        for (int i = 0; i < 4; i++) {
            mn[i] = fmaxf(m_[i], rmax[i]);
            al[i] = __expf(m_[i] - mn[i]);
            m_[i] = mn[i];
        }

        float rs[4] = {0.f, 0.f, 0.f, 0.f};
        #pragma unroll
        for (int n = 0; n < 8; n++) {
            #pragma unroll
            for (int mb = 0; mb < 2; mb++) {
                s[mb][n][0] = __expf(s[mb][n][0] - mn[mb*2  ]);
                s[mb][n][1] = __expf(s[mb][n][1] - mn[mb*2  ]);
                s[mb][n][2] = __expf(s[mb][n][2] - mn[mb*2+1]);
                s[mb][n][3] = __expf(s[mb][n][3] - mn[mb*2+1]);
                rs[mb*2  ] += s[mb][n][0] + s[mb][n][1];
                rs[mb*2+1] += s[mb][n][2] + s[mb][n][3];
            }
        }
        #pragma unroll
        for (int i = 0; i < 4; i++) {
            rs[i] += __shfl_xor_sync(0xffffffffu, rs[i], 1);
            rs[i] += __shfl_xor_sync(0xffffffffu, rs[i], 2);
            l_[i] = l_[i] * al[i] + rs[i];
        }

        #pragma unroll
        for (int mb = 0; mb < 2; mb++)
            #pragma unroll
            for (int n = 0; n < 8; n++) {
                s[mb][n][0] = __uint_as_float(f2tf32(s[mb][n][0]));
                s[mb][n][1] = __uint_as_float(f2tf32(s[mb][n][1]));
                s[mb][n][2] = __uint_as_float(f2tf32(s[mb][n][2]));
                s[mb][n][3] = __uint_as_float(f2tf32(s[mb][n][3]));
                o[mb][n][0] *= al[mb*2  ];
                o[mb][n][1] *= al[mb*2  ];
                o[mb][n][2] *= al[mb*2+1];
                o[mb][n][3] *= al[mb*2+1];
            }

        #pragma unroll
        for (int k0i = 0; k0i < 8; k0i++) {
            int kr = k0i * 8;
            uint32_t bf[8][2];
            #pragma unroll
            for (int n = 0; n < 8; n++) {
                bf[n][0] = Vs[(kr + tig    ) * 68 + n * 8 + g];
                bf[n][1] = Vs[(kr + tig + 4) * 68 + n * 8 + g];
            }
            #pragma unroll
            for (int mb = 0; mb < 2; mb++) {
                float v00 = __shfl_sync(0xffffffffu, s[mb][k0i][0], srcA);
                float v01 = __shfl_sync(0xffffffffu, s[mb][k0i][1], srcA);
                float v10 = __shfl_sync(0xffffffffu, s[mb][k0i][2], srcA);
                float v11 = __shfl_sync(0xffffffffu, s[mb][k0i][3], srcA);
                float w00 = __shfl_sync(0xffffffffu, s[mb][k0i][0], srcB);
                float w01 = __shfl_sync(0xffffffffu, s[mb][k0i][1], srcB);
                float w10 = __shfl_sync(0xffffffffu, s[mb][k0i][2], srcB);
                float w11 = __shfl_sync(0xffffffffu, s[mb][k0i][3], srcB);
                uint32_t af[4];
                af[0] = __float_as_uint(podd ? v01 : v00);
                af[1] = __float_as_uint(podd ? v11 : v10);
                af[2] = __float_as_uint(podd ? w01 : w00);
                af[3] = __float_as_uint(podd ? w11 : w10);
                #pragma unroll
                for (int n = 0; n < 8; n++)
                    mma_tf32(o[mb][n], af, bf[n]);
            }
        }
    }

    float il[4];
    #pragma unroll
    for (int i = 0; i < 4; i++) il[i] = 1.f / l_[i];

    #pragma unroll
    for (int mb = 0; mb < 2; mb++) {
        int s0 = qt * 256 + rw + mb * 16 + g;
        int s1 = s0 + 8;
        size_t base0 = (((size_t)b * Sv + s0) * Hv + h) * DHv;
        size_t base1 = (((size_t)b * Sv + s1) * Hv + h) * DHv;
        #pragma unroll
        for (int n = 0; n < 8; n++) {
            int dh = n * 8 + 2 * tig;
            g_ctx[base0 + dh    ] = f2tf32(o[mb][n][0] * il[mb*2  ]);
            g_ctx[base0 + dh + 1] = f2tf32(o[mb][n][1] * il[mb*2  ]);
            g_ctx[base1 + dh    ] = f2tf32(o[mb][n][2] * il[mb*2+1]);
            g_ctx[base1 + dh + 1] = f2tf32(o[mb][n][3] * il[mb*2+1]);
        }
    }
}

extern "C" void kernel_launch(void* const* d_in, const int* in_sizes, int n_in,
                              void* d_out, int out_size)
{
    const float* query = (const float*)d_in[0];
    const float* key   = (const float*)d_in[1];
    const float* value = (const float*)d_in[2];
    const int*   mask  = (const int*)  d_in[3];
    const float* Wq    = (const float*)d_in[4];
    const float* bq    = (const float*)d_in[5];
    const float* Wk    = (const float*)d_in[6];
    const float* bk    = (const float*)d_in[7];
    const float* Wv    = (const float*)d_in[8];
    const float* bv    = (const float*)d_in[9];
    const float* Wo    = (const float*)d_in[10];
    const float* bo    = (const float*)d_in[11];
    float* out = (float*)d_out;

    uint32_t *qin, *kin, *vin, *wq, *wk, *wv, *wo, *gq, *gk, *gv, *gctx;
    cudaGetSymbolAddress((void**)&qin,  g_qin);
    cudaGetSymbolAddress((void**)&kin,  g_kin);
    cudaGetSymbolAddress((void**)&vin,  g_vin);
    cudaGetSymbolAddress((void**)&wq,   g_wq);
    cudaGetSymbolAddress((void**)&wk,   g_wk);
    cudaGetSymbolAddress((void**)&wv,   g_wv);
    cudaGetSymbolAddress((void**)&wo,   g_wo);
    cudaGetSymbolAddress((void**)&gq,   g_q);
    cudaGetSymbolAddress((void**)&gk,   g_k);
    cudaGetSymbolAddress((void**)&gv,   g_v);
    cudaGetSymbolAddress((void**)&gctx, g_ctx);

    const int smem_gemm = GEMM_SMEM_WORDS * 4;           // 165,888
    const int smem_attn = (256 * 68 + 4 * 64 * 68) * 4;  // 139,264
    cudaFuncSetAttribute(proj_qkv,   cudaFuncAttributeMaxDynamicSharedMemorySize, smem_gemm);
    cudaFuncSetAttribute(gemm_out,   cudaFuncAttributeMaxDynamicSharedMemorySize, smem_gemm);
    cudaFuncSetAttribute(flash_attn, cudaFuncAttributeMaxDynamicSharedMemorySize, smem_attn);

    const int NIN4 = Mv * Dv / 4;
    const int NW4  = Dv * Dv / 4;
    cvt3_kernel<<<dim3(1024, 3), 256>>>((const float4*)query, (const float4*)key, (const float4*)value,
                                        (uint4*)qin, (uint4*)kin, (uint4*)vin, NIN4);
    cvt4_kernel<<<dim3(256, 4), 256>>>((const float4*)Wq, (const float4*)Wk, (const float4*)Wv, (const float4*)Wo,
                                       (uint4*)wq, (uint4*)wk, (uint4*)wv, (uint4*)wo, NW4);

    proj_qkv<<<dim3(Dv / 256, Mv / 128, 3), 256, smem_gemm>>>(
        qin, kin, vin, wq, wk, wv, bq, bk, bv, gq, gk, gv);

    flash_attn<<<dim3(Sv / 256, Bv * Hv), 256, smem_attn>>>(mask);

    gemm_out<<<dim3(Dv / 256, Mv / 128), 256, smem_gemm>>>(gctx, wo, bo, out);
}

// round 13
// speedup vs baseline: 1.0186x; 1.0186x over previous
#include <cuda_runtime.h>
#include <cstdint>

#define Bv 4
#define Sv 2048
#define Dv 1024
#define Hv 16
#define DHv 64
#define Mv (Bv*Sv)          // 8192

// Scratch (tf32 bit patterns everywhere)
__device__ uint32_t g_qin[Mv*Dv];
__device__ uint32_t g_kin[Mv*Dv];
__device__ uint32_t g_vin[Mv*Dv];
__device__ uint32_t g_wq[Dv*Dv];
__device__ uint32_t g_wk[Dv*Dv];
__device__ uint32_t g_wv[Dv*Dv];
__device__ uint32_t g_wo[Dv*Dv];
__device__ uint32_t g_q[Mv*Dv];    // [b,h,s,dh]
__device__ uint32_t g_k[Mv*Dv];
__device__ uint32_t g_v[Mv*Dv];
__device__ uint32_t g_ctx[Mv*Dv];  // [b,s,h,dh]

__device__ __forceinline__ uint32_t f2tf32(float x) {
    uint32_t r;
    asm("cvt.rna.tf32.f32 %0, %1;" : "=r"(r) : "f"(x));
    return r;
}

__device__ __forceinline__ void mma_tf32(float c[4], const uint32_t a[4], const uint32_t b[2]) {
    asm volatile(
        "mma.sync.aligned.m16n8k8.row.col.f32.tf32.tf32.f32 "
        "{%0,%1,%2,%3}, {%4,%5,%6,%7}, {%8,%9}, {%0,%1,%2,%3};\n"
        : "+f"(c[0]), "+f"(c[1]), "+f"(c[2]), "+f"(c[3])
        : "r"(a[0]), "r"(a[1]), "r"(a[2]), "r"(a[3]), "r"(b[0]), "r"(b[1]));
}

__device__ __forceinline__ void cpa16(uint32_t saddr, const void* gptr) {
    asm volatile("cp.async.cg.shared.global [%0], [%1], 16;" :: "r"(saddr), "l"(gptr));
}
__device__ __forceinline__ void cpa_commit() {
    asm volatile("cp.async.commit_group;" ::: "memory");
}

// ---------------- conversions ----------------

__global__ __launch_bounds__(256) void cvt3_kernel(
    const float4* __restrict__ a, const float4* __restrict__ b, const float4* __restrict__ c,
    uint4* __restrict__ oa, uint4* __restrict__ ob, uint4* __restrict__ oc, int n4)
{
    const float4* in  = (blockIdx.y == 0) ? a  : (blockIdx.y == 1) ? b  : c;
    uint4*        out = (blockIdx.y == 0) ? oa : (blockIdx.y == 1) ? ob : oc;
    int i = blockIdx.x * blockDim.x + threadIdx.x;
    int stride = gridDim.x * blockDim.x;
    for (; i < n4; i += stride) {
        float4 v = in[i];
        out[i] = make_uint4(f2tf32(v.x), f2tf32(v.y), f2tf32(v.z), f2tf32(v.w));
    }
}

__global__ __launch_bounds__(256) void cvt4_kernel(
    const float4* __restrict__ a, const float4* __restrict__ b,
    const float4* __restrict__ c, const float4* __restrict__ d,
    uint4* __restrict__ oa, uint4* __restrict__ ob,
    uint4* __restrict__ oc, uint4* __restrict__ od, int n4)
{
    const float4* in  = (blockIdx.y == 0) ? a  : (blockIdx.y == 1) ? b  : (blockIdx.y == 2) ? c  : d;
    uint4*        out = (blockIdx.y == 0) ? oa : (blockIdx.y == 1) ? ob : (blockIdx.y == 2) ? oc : od;
    int i = blockIdx.x * blockDim.x + threadIdx.x;
    int stride = gridDim.x * blockDim.x;
    for (; i < n4; i += stride) {
        float4 v = in[i];
        out[i] = make_uint4(f2tf32(v.x), f2tf32(v.y), f2tf32(v.z), f2tf32(v.w));
    }
}

// ---------------- GEMM: R7-proven 128x128 tile, warp 64x32, 3-stage cp.async ----------------

__device__ __forceinline__ void gemm_body(
    const uint32_t* __restrict__ A, const uint32_t* __restrict__ W,
    const float* __restrict__ bias, void* __restrict__ Cout,
    int bm, int bn, int scatter, uint32_t* smg)
{
    const int ASZ = 128 * 36;
    uint32_t* As = smg;
    uint32_t* Bs = smg + 3 * ASZ;
    const uint32_t smb = (uint32_t)__cvta_generic_to_shared(smg);

    const int tid  = threadIdx.x;
    const int warp = tid >> 5;
    const int lane = tid & 31;
    const int wm   = (warp >> 2) * 64;
    const int wn   = (warp & 3) * 32;
    const int g    = lane >> 2;
    const int tig  = lane & 3;

    float acc[4][4][4];
    #pragma unroll
    for (int i = 0; i < 4; i++)
        #pragma unroll
        for (int j = 0; j < 4; j++)
            #pragma unroll
            for (int t = 0; t < 4; t++) acc[i][j][t] = 0.f;

    auto issue = [&](int st, int kt) {
        #pragma unroll
        for (int u = 0; u < 4; u++) {
            int id = tid + u * 256;
            int r = id >> 3, c = (id & 7) << 2;
            cpa16(smb + (uint32_t)(st * ASZ + r * 36 + c) * 4,
                  &A[(size_t)(bm + r) * Dv + kt + c]);
            cpa16(smb + (uint32_t)(3 * ASZ + st * ASZ + r * 36 + c) * 4,
                  &W[(size_t)(bn + r) * Dv + kt + c]);
        }
        cpa_commit();
    };

    issue(0, 0);
    issue(1, 32);

    for (int t = 0; t < 32; t++) {
        if (t == 31) asm volatile("cp.async.wait_group 0;" ::: "memory");
        else         asm volatile("cp.async.wait_group 1;" ::: "memory");
        __syncthreads();
        if (t + 2 < 32) issue((t + 2) % 3, (t + 2) * 32);

        const uint32_t* Ab = As + (t % 3) * ASZ;
        const uint32_t* Bb = Bs + (t % 3) * ASZ;

        #pragma unroll
        for (int k0 = 0; k0 < 32; k0 += 8) {
            uint32_t af[4][4], bf[4][2];
            #pragma unroll
            for (int i = 0; i < 4; i++) {
                int r0 = wm + i * 16;
                af[i][0] = Ab[(r0 + g    ) * 36 + k0 + tig    ];
                af[i][1] = Ab[(r0 + g + 8) * 36 + k0 + tig    ];
                af[i][2] = Ab[(r0 + g    ) * 36 + k0 + tig + 4];
                af[i][3] = Ab[(r0 + g + 8) * 36 + k0 + tig + 4];
            }
            #pragma unroll
            for (int j = 0; j < 4; j++) {
                int c0 = wn + j * 8;
                bf[j][0] = Bb[(c0 + g) * 36 + k0 + tig    ];
                bf[j][1] = Bb[(c0 + g) * 36 + k0 + tig + 4];
            }
            #pragma unroll
            for (int i = 0; i < 4; i++)
                #pragma unroll
                for (int j = 0; j < 4; j++)
                    mma_tf32(acc[i][j], af[i], bf[j]);
        }
        __syncthreads();
    }

    #pragma unroll
    for (int i = 0; i < 4; i++) {
        #pragma unroll
        for (int j = 0; j < 4; j++) {
            int r0 = bm + wm + i * 16 + g;
            int r1 = r0 + 8;
            int c0 = bn + wn + j * 8 + 2 * tig;
            float b0 = bias[c0], b1 = bias[c0 + 1];
            float v00 = acc[i][j][0] + b0, v01 = acc[i][j][1] + b1;
            float v10 = acc[i][j][2] + b0, v11 = acc[i][j][3] + b1;
            if (scatter) {
                uint32_t* C = (uint32_t*)Cout;
                int b_0 = r0 >> 11, s_0 = r0 & 2047;
                int b_1 = r1 >> 11, s_1 = r1 & 2047;
                int h = c0 >> 6, dh = c0 & 63;
                size_t i0 = ((((size_t)b_0 * Hv + h) * Sv) + s_0) * DHv + dh;
                size_t i1 = ((((size_t)b_1 * Hv + h) * Sv) + s_1) * DHv + dh;
                C[i0] = f2tf32(v00); C[i0 + 1] = f2tf32(v01);
                C[i1] = f2tf32(v10); C[i1 + 1] = f2tf32(v11);
            } else {
                float* C = (float*)Cout;
                C[(size_t)r0 * Dv + c0] = v00; C[(size_t)r0 * Dv + c0 + 1] = v01;
                C[(size_t)r1 * Dv + c0] = v10; C[(size_t)r1 * Dv + c0 + 1] = v11;
            }
        }
    }
}

__global__ __launch_bounds__(256) void proj_qkv(
    const uint32_t* __restrict__ Aq, const uint32_t* __restrict__ Ak, const uint32_t* __restrict__ Av,
    const uint32_t* __restrict__ Wq, const uint32_t* __restrict__ Wk, const uint32_t* __restrict__ Wv,
    const float* __restrict__ bq, const float* __restrict__ bk, const float* __restrict__ bv,
    uint32_t* __restrict__ Oq, uint32_t* __restrict__ Ok, uint32_t* __restrict__ Ov)
{
    extern __shared__ uint32_t smg[];
    const uint32_t* A = (blockIdx.z == 0) ? Aq : (blockIdx.z == 1) ? Ak : Av;
    const uint32_t* W = (blockIdx.z == 0) ? Wq : (blockIdx.z == 1) ? Wk : Wv;
    const float*    bb = (blockIdx.z == 0) ? bq : (blockIdx.z == 1) ? bk : bv;
    uint32_t*       O = (blockIdx.z == 0) ? Oq : (blockIdx.z == 1) ? Ok : Ov;
    gemm_body(A, W, bb, O, blockIdx.y * 128, blockIdx.x * 128, 1, smg);
}

__global__ __launch_bounds__(256) void gemm_out(
    const uint32_t* __restrict__ A, const uint32_t* __restrict__ W,
    const float* __restrict__ bias, float* __restrict__ C)
{
    extern __shared__ uint32_t smg[];
    gemm_body(A, W, bias, C, blockIdx.y * 128, blockIdx.x * 128, 0, smg);
}

// ---------------- flash attention: R7 structure + base-2 softmax ----------------
// Br=256 (8 warps x 32 q-rows, 2 m-blocks), Bc=64.
__global__ __launch_bounds__(256) void flash_attn(const int* __restrict__ mask)
{
    extern __shared__ uint32_t smf[];
    const int QOFF = 0;
    const int KOFF = 256 * 68;
    const int VOFF = KOFF + 2 * 64 * 68;
    const int TSZ  = 64 * 68;
    const uint32_t smb = (uint32_t)__cvta_generic_to_shared(smf);

    const int qt  = blockIdx.x;
    const int bh  = blockIdx.y;
    const int b   = bh >> 4;
    const int h   = bh & 15;
    const uint32_t* Qg = g_q + (size_t)bh * Sv * DHv + (size_t)qt * 256 * DHv;
    const uint32_t* Kg = g_k + (size_t)bh * Sv * DHv;
    const uint32_t* Vg = g_v + (size_t)bh * Sv * DHv;
    const int* mrow = mask + b * Sv;

    const int tid  = threadIdx.x;
    const int warp = tid >> 5;
    const int lane = tid & 31;
    const int g    = lane >> 2;
    const int tig  = lane & 3;
    const int rw   = warp * 32;

    #pragma unroll
    for (int i = tid; i < 256 * 16; i += 256) {
        int r = i >> 4, c = (i & 15) << 2;
        *(uint4*)&smf[QOFF + r * 68 + c] = *(const uint4*)&Qg[r * 64 + c];
    }

    auto issue_kv = [&](int st, int jt) {
        #pragma unroll
        for (int u = 0; u < 4; u++) {
            int id = tid + u * 256;
            int r = id >> 4, c = (id & 15) << 2;
            cpa16(smb + (uint32_t)(KOFF + st * TSZ + r * 68 + c) * 4,
                  &Kg[(jt * 64 + r) * 64 + c]);
            cpa16(smb + (uint32_t)(VOFF + st * TSZ + r * 68 + c) * 4,
                  &Vg[(jt * 64 + r) * 64 + c]);
        }
        cpa_commit();
    };

    float m_[4], l_[4];
    #pragma unroll
    for (int i = 0; i < 4; i++) { m_[i] = -1e30f; l_[i] = 0.f; }

    float o[2][8][4];
    #pragma unroll
    for (int mb = 0; mb < 2; mb++)
        #pragma unroll
        for (int n = 0; n < 8; n++)
            #pragma unroll
            for (int q = 0; q < 4; q++) o[mb][n][q] = 0.f;

    // base-2 softmax: scale2 = (1/sqrt(1024)) * log2(e)
    const float scale2 = 0.0450842298f;
    const int srcA = (lane & 28) | (tig >> 1);
    const int srcB = srcA + 2;
    const bool podd = (tig & 1) != 0;

    issue_kv(0, 0);

    for (int jt = 0; jt < Sv / 64; jt++) {
        asm volatile("cp.async.wait_group 0;" ::: "memory");
        __syncthreads();
        if (jt + 1 < Sv / 64) issue_kv((jt + 1) & 1, jt + 1);

        const uint32_t* Ks = smf + KOFF + (jt & 1) * TSZ;
        const uint32_t* Vs = smf + VOFF + (jt & 1) * TSZ;

        float s[2][8][4];
        #pragma unroll
        for (int mb = 0; mb < 2; mb++)
            #pragma unroll
            for (int n = 0; n < 8; n++)
                #pragma unroll
                for (int q = 0; q < 4; q++) s[mb][n][q] = 0.f;

        #pragma unroll
        for (int k0 = 0; k0 < 64; k0 += 8) {
            uint32_t aq[2][4];
            #pragma unroll
            for (int mb = 0; mb < 2; mb++) {
                int r0 = rw + mb * 16;
                aq[mb][0] = smf[QOFF + (r0 + g    ) * 68 + k0 + tig    ];
                aq[mb][1] = smf[QOFF + (r0 + g + 8) * 68 + k0 + tig    ];
                aq[mb][2] = smf[QOFF + (r0 + g    ) * 68 + k0 + tig + 4];
                aq[mb][3] = smf[QOFF + (r0 + g + 8) * 68 + k0 + tig + 4];
            }
            #pragma unroll
            for (int n = 0; n < 8; n++) {
                uint32_t bf[2];
                bf[0] = Ks[(n * 8 + g) * 68 + k0 + tig    ];
                bf[1] = Ks[(n * 8 + g) * 68 + k0 + tig + 4];
                mma_tf32(s[0][n], aq[0], bf);
                mma_tf32(s[1][n], aq[1], bf);
            }
        }

        float rmax[4];
        #pragma unroll
        for (int i = 0; i < 4; i++) rmax[i] = -1e30f;
        #pragma unroll
        for (int n = 0; n < 8; n++) {
            int c0 = jt * 64 + n * 8 + 2 * tig;
            float msk0 = mrow[c0]     ? 0.f : -1e30f;
            float msk1 = mrow[c0 + 1] ? 0.f : -1e30f;
            #pragma unroll
            for (int mb = 0; mb < 2; mb++) {
                s[mb][n][0] = s[mb][n][0] * scale2 + msk0;
                s[mb][n][1] = s[mb][n][1] * scale2 + msk1;
                s[mb][n][2] = s[mb][n][2] * scale2 + msk0;
                s[mb][n][3] = s[mb][n][3] * scale2 + msk1;
                rmax[mb*2  ] = fmaxf(rmax[mb*2  ], fmaxf(s[mb][n][0], s[mb][n][1]));
                rmax[mb*2+1] = fmaxf(rmax[mb*2+1], fmaxf(s[mb][n][2], s[mb][n][3]));
            }
        }
        #pragma unroll
        for (int i = 0; i < 4; i++) {
            rmax[i] = fmaxf(rmax[i], __shfl_xor_sync(0xffffffffu, rmax[i], 1));
            rmax[i] = fmaxf(rmax[i], __shfl_xor_sync(0xffffffffu, rmax[i], 2));
        }

        float al[4], mn[4];
        #pragma unroll
        for (int i = 0; i < 4; i++) {
            mn[i] = fmaxf(m_[i], rmax[i]);
            al[i] = exp2f(m_[i] - mn[i]);
            m_[i] = mn[i];
        }

        float rs[4] = {0.f, 0.f, 0.f, 0.f};
        #pragma unroll
        for (int n = 0; n < 8; n++) {
            #pragma unroll
            for (int mb = 0; mb < 2; mb++) {
                s[mb][n][0] = exp2f(s[mb][n][0] - mn[mb*2  ]);
                s[mb][n][1] = exp2f(s[mb][n][1] - mn[mb*2  ]);
                s[mb][n][2] = exp2f(s[mb][n][2] - mn[mb*2+1]);
                s[mb][n][3] = exp2f(s[mb][n][3] - mn[mb*2+1]);
                rs[mb*2  ] += s[mb][n][0] + s[mb][n][1];
                rs[mb*2+1] += s[mb][n][2] + s[mb][n][3];
            }
        }
        #pragma unroll
        for (int i = 0; i < 4; i++) {
            rs[i] += __shfl_xor_sync(0xffffffffu, rs[i], 1);
            rs[i] += __shfl_xor_sync(0xffffffffu, rs[i], 2);
            l_[i] = l_[i] * al[i] + rs[i];
        }

        #pragma unroll
        for (int mb = 0; mb < 2; mb++)
            #pragma unroll
            for (int n = 0; n < 8; n++) {
                s[mb][n][0] = __uint_as_float(f2tf32(s[mb][n][0]));
                s[mb][n][1] = __uint_as_float(f2tf32(s[mb][n][1]));
                s[mb][n][2] = __uint_as_float(f2tf32(s[mb][n][2]));
                s[mb][n][3] = __uint_as_float(f2tf32(s[mb][n][3]));
                o[mb][n][0] *= al[mb*2  ];
                o[mb][n][1] *= al[mb*2  ];
                o[mb][n][2] *= al[mb*2+1];
                o[mb][n][3] *= al[mb*2+1];
            }

        #pragma unroll
        for (int k0i = 0; k0i < 8; k0i++) {
            int kr = k0i * 8;
            uint32_t bf[8][2];
            #pragma unroll
            for (int n = 0; n < 8; n++) {
                bf[n][0] = Vs[(kr + tig    ) * 68 + n * 8 + g];
                bf[n][1] = Vs[(kr + tig + 4) * 68 + n * 8 + g];
            }
            #pragma unroll
            for (int mb = 0; mb < 2; mb++) {
                float v00 = __shfl_sync(0xffffffffu, s[mb][k0i][0], srcA);
                float v01 = __shfl_sync(0xffffffffu, s[mb][k0i][1], srcA);
                float v10 = __shfl_sync(0xffffffffu, s[mb][k0i][2], srcA);
                float v11 = __shfl_sync(0xffffffffu, s[mb][k0i][3], srcA);
                float w00 = __shfl_sync(0xffffffffu, s[mb][k0i][0], srcB);
                float w01 = __shfl_sync(0xffffffffu, s[mb][k0i][1], srcB);
                float w10 = __shfl_sync(0xffffffffu, s[mb][k0i][2], srcB);
                float w11 = __shfl_sync(0xffffffffu, s[mb][k0i][3], srcB);
                uint32_t af[4];
                af[0] = __float_as_uint(podd ? v01 : v00);
                af[1] = __float_as_uint(podd ? v11 : v10);
                af[2] = __float_as_uint(podd ? w01 : w00);
                af[3] = __float_as_uint(podd ? w11 : w10);
                #pragma unroll
                for (int n = 0; n < 8; n++)
                    mma_tf32(o[mb][n], af, bf[n]);
            }
        }
    }

    float il[4];
    #pragma unroll
    for (int i = 0; i < 4; i++) il[i] = 1.f / l_[i];

    #pragma unroll
    for (int mb = 0; mb < 2; mb++) {
        int s0 = qt * 256 + rw + mb * 16 + g;
        int s1 = s0 + 8;
        size_t base0 = (((size_t)b * Sv + s0) * Hv + h) * DHv;
        size_t base1 = (((size_t)b * Sv + s1) * Hv + h) * DHv;
        #pragma unroll
        for (int n = 0; n < 8; n++) {
            int dh = n * 8 + 2 * tig;
            g_ctx[base0 + dh    ] = f2tf32(o[mb][n][0] * il[mb*2  ]);
            g_ctx[base0 + dh + 1] = f2tf32(o[mb][n][1] * il[mb*2  ]);
            g_ctx[base1 + dh    ] = f2tf32(o[mb][n][2] * il[mb*2+1]);
            g_ctx[base1 + dh + 1] = f2tf32(o[mb][n][3] * il[mb*2+1]);
        }
    }
}

extern "C" void kernel_launch(void* const* d_in, const int* in_sizes, int n_in,
                              void* d_out, int out_size)
{
    const float* query = (const float*)d_in[0];
    const float* key   = (const float*)d_in[1];
    const float* value = (const float*)d_in[2];
    const int*   mask  = (const int*)  d_in[3];
    const float* Wq    = (const float*)d_in[4];
    const float* bq    = (const float*)d_in[5];
    const float* Wk    = (const float*)d_in[6];
    const float* bk    = (const float*)d_in[7];
    const float* Wv    = (const float*)d_in[8];
    const float* bv    = (const float*)d_in[9];
    const float* Wo    = (const float*)d_in[10];
    const float* bo    = (const float*)d_in[11];
    float* out = (float*)d_out;

    uint32_t *qin, *kin, *vin, *wq, *wk, *wv, *wo, *gq, *gk, *gv, *gctx;
    cudaGetSymbolAddress((void**)&qin,  g_qin);
    cudaGetSymbolAddress((void**)&kin,  g_kin);
    cudaGetSymbolAddress((void**)&vin,  g_vin);
    cudaGetSymbolAddress((void**)&wq,   g_wq);
    cudaGetSymbolAddress((void**)&wk,   g_wk);
    cudaGetSymbolAddress((void**)&wv,   g_wv);
    cudaGetSymbolAddress((void**)&wo,   g_wo);
    cudaGetSymbolAddress((void**)&gq,   g_q);
    cudaGetSymbolAddress((void**)&gk,   g_k);
    cudaGetSymbolAddress((void**)&gv,   g_v);
    cudaGetSymbolAddress((void**)&gctx, g_ctx);

    const int smem_gemm = 6 * 128 * 36 * 4;              // 110592 (2 CTAs/SM)
    const int smem_attn = (256 * 68 + 4 * 64 * 68) * 4;  // 139264
    cudaFuncSetAttribute(proj_qkv,   cudaFuncAttributeMaxDynamicSharedMemorySize, smem_gemm);
    cudaFuncSetAttribute(gemm_out,   cudaFuncAttributeMaxDynamicSharedMemorySize, smem_gemm);
    cudaFuncSetAttribute(flash_attn, cudaFuncAttributeMaxDynamicSharedMemorySize, smem_attn);

    const int NIN4 = Mv * Dv / 4;
    const int NW4  = Dv * Dv / 4;
    cvt3_kernel<<<dim3(1024, 3), 256>>>((const float4*)query, (const float4*)key, (const float4*)value,
                                        (uint4*)qin, (uint4*)kin, (uint4*)vin, NIN4);
    cvt4_kernel<<<dim3(256, 4), 256>>>((const float4*)Wq, (const float4*)Wk, (const float4*)Wv, (const float4*)Wo,
                                       (uint4*)wq, (uint4*)wk, (uint4*)wv, (uint4*)wo, NW4);

    proj_qkv<<<dim3(Dv / 128, Mv / 128, 3), 256, smem_gemm>>>(
        qin, kin, vin, wq, wk, wv, bq, bk, bv, gq, gk, gv);

    flash_attn<<<dim3(Sv / 256, Bv * Hv), 256, smem_attn>>>(mask);

    gemm_out<<<dim3(Dv / 128, Mv / 128), 256, smem_gemm>>>(gctx, wo, bo, out);
}

// round 14
// speedup vs baseline: 1.0646x; 1.0451x over previous
#include <cuda_runtime.h>
#include <cstdint>

#define Bv 4
#define Sv 2048
#define Dv 1024
#define Hv 16
#define DHv 64
#define Mv (Bv*Sv)          // 8192

// Scratch (tf32 bit patterns everywhere)
__device__ uint32_t g_qin[Mv*Dv];
__device__ uint32_t g_kin[Mv*Dv];
__device__ uint32_t g_vin[Mv*Dv];
__device__ uint32_t g_wq[Dv*Dv];
__device__ uint32_t g_wk[Dv*Dv];
__device__ uint32_t g_wv[Dv*Dv];
__device__ uint32_t g_wo[Dv*Dv];
__device__ uint32_t g_q[Mv*Dv];    // [b,h,s,dh]
__device__ uint32_t g_k[Mv*Dv];
__device__ uint32_t g_v[Mv*Dv];
__device__ uint32_t g_ctx[Mv*Dv];  // [b,s,h,dh]

__device__ __forceinline__ uint32_t f2tf32(float x) {
    uint32_t r;
    asm("cvt.rna.tf32.f32 %0, %1;" : "=r"(r) : "f"(x));
    return r;
}

__device__ __forceinline__ void mma_tf32(float c[4], const uint32_t a[4], const uint32_t b[2]) {
    asm volatile(
        "mma.sync.aligned.m16n8k8.row.col.f32.tf32.tf32.f32 "
        "{%0,%1,%2,%3}, {%4,%5,%6,%7}, {%8,%9}, {%0,%1,%2,%3};\n"
        : "+f"(c[0]), "+f"(c[1]), "+f"(c[2]), "+f"(c[3])
        : "r"(a[0]), "r"(a[1]), "r"(a[2]), "r"(a[3]), "r"(b[0]), "r"(b[1]));
}

// ldmatrix x4: loads 4 8x8 b16 matrices; for 32-bit (tf32) data each matrix
// delivers one 32-bit element per lane at [lane/4][lane%4] (32-bit cols).
__device__ __forceinline__ void ldsm_x4(uint32_t& r0, uint32_t& r1, uint32_t& r2, uint32_t& r3,
                                        uint32_t addr) {
    asm volatile("ldmatrix.sync.aligned.m8n8.x4.shared.b16 {%0,%1,%2,%3}, [%4];"
        : "=r"(r0), "=r"(r1), "=r"(r2), "=r"(r3) : "r"(addr));
}

__device__ __forceinline__ void cpa16(uint32_t saddr, const void* gptr) {
    asm volatile("cp.async.cg.shared.global [%0], [%1], 16;" :: "r"(saddr), "l"(gptr));
}
__device__ __forceinline__ void cpa_commit() {
    asm volatile("cp.async.commit_group;" ::: "memory");
}

// ---------------- conversions ----------------

__global__ __launch_bounds__(256) void cvt3_kernel(
    const float4* __restrict__ a, const float4* __restrict__ b, const float4* __restrict__ c,
    uint4* __restrict__ oa, uint4* __restrict__ ob, uint4* __restrict__ oc, int n4)
{
    const float4* in  = (blockIdx.y == 0) ? a  : (blockIdx.y == 1) ? b  : c;
    uint4*        out = (blockIdx.y == 0) ? oa : (blockIdx.y == 1) ? ob : oc;
    int i = blockIdx.x * blockDim.x + threadIdx.x;
    int stride = gridDim.x * blockDim.x;
    for (; i < n4; i += stride) {
        float4 v = in[i];
        out[i] = make_uint4(f2tf32(v.x), f2tf32(v.y), f2tf32(v.z), f2tf32(v.w));
    }
}

__global__ __launch_bounds__(256) void cvt4_kernel(
    const float4* __restrict__ a, const float4* __restrict__ b,
    const float4* __restrict__ c, const float4* __restrict__ d,
    uint4* __restrict__ oa, uint4* __restrict__ ob,
    uint4* __restrict__ oc, uint4* __restrict__ od, int n4)
{
    const float4* in  = (blockIdx.y == 0) ? a  : (blockIdx.y == 1) ? b  : (blockIdx.y == 2) ? c  : d;
    uint4*        out = (blockIdx.y == 0) ? oa : (blockIdx.y == 1) ? ob : (blockIdx.y == 2) ? oc : od;
    int i = blockIdx.x * blockDim.x + threadIdx.x;
    int stride = gridDim.x * blockDim.x;
    for (; i < n4; i += stride) {
        float4 v = in[i];
        out[i] = make_uint4(f2tf32(v.x), f2tf32(v.y), f2tf32(v.z), f2tf32(v.w));
    }
}

// ---------------- GEMM: 128x128 tile, warp 64x32, 3-stage cp.async, LDSM fragments ----------------

__device__ __forceinline__ void gemm_body(
    const uint32_t* __restrict__ A, const uint32_t* __restrict__ W,
    const float* __restrict__ bias, void* __restrict__ Cout,
    int bm, int bn, int scatter, uint32_t* smg)
{
    const int ASZ = 128 * 36;
    const uint32_t smb = (uint32_t)__cvta_generic_to_shared(smg);

    const int tid  = threadIdx.x;
    const int warp = tid >> 5;
    const int lane = tid & 31;
    const int wm   = (warp >> 2) * 64;
    const int wn   = (warp & 3) * 32;
    const int g    = lane >> 2;
    const int tig  = lane & 3;

    // ldmatrix lane addressing:
    // A-fragment x4: m0 rows+0 left, m1 rows+8 left, m2 rows+0 right, m3 rows+8 right
    const int arow  = (lane & 7) + ((lane >> 3) & 1) * 8;
    const int ahalf = (lane >> 4) * 16;                    // bytes
    // B-fragment-pair x4: m0 j0 left, m1 j0 right, m2 j1 left, m3 j1 right
    const int brow  = (lane & 7) + (lane >> 4) * 8;
    const int bhalf = ((lane >> 3) & 1) * 16;              // bytes

    float acc[4][4][4];
    #pragma unroll
    for (int i = 0; i < 4; i++)
        #pragma unroll
        for (int j = 0; j < 4; j++)
            #pragma unroll
            for (int t = 0; t < 4; t++) acc[i][j][t] = 0.f;

    auto issue = [&](int st, int kt) {
        #pragma unroll
        for (int u = 0; u < 4; u++) {
            int id = tid + u * 256;
            int r = id >> 3, c = (id & 7) << 2;
            cpa16(smb + (uint32_t)(st * ASZ + r * 36 + c) * 4,
                  &A[(size_t)(bm + r) * Dv + kt + c]);
            cpa16(smb + (uint32_t)(3 * ASZ + st * ASZ + r * 36 + c) * 4,
                  &W[(size_t)(bn + r) * Dv + kt + c]);
        }
        cpa_commit();
    };

    issue(0, 0);
    issue(1, 32);

    for (int t = 0; t < 32; t++) {
        if (t == 31) asm volatile("cp.async.wait_group 0;" ::: "memory");
        else         asm volatile("cp.async.wait_group 1;" ::: "memory");
        __syncthreads();
        if (t + 2 < 32) issue((t + 2) % 3, (t + 2) * 32);

        const uint32_t stA = smb + (uint32_t)((t % 3) * ASZ) * 4;
        const uint32_t stB = smb + (uint32_t)(3 * ASZ + (t % 3) * ASZ) * 4;
        const uint32_t aAddr = stA + (uint32_t)((wm + arow) * 36) * 4 + ahalf;
        const uint32_t bAddr = stB + (uint32_t)((wn + brow) * 36) * 4 + bhalf;

        #pragma unroll
        for (int k0 = 0; k0 < 32; k0 += 8) {
            uint32_t af[4][4], bf[4][2];
            #pragma unroll
            for (int i = 0; i < 4; i++)
                ldsm_x4(af[i][0], af[i][1], af[i][2], af[i][3],
                        aAddr + (uint32_t)(i * 16 * 36 + k0) * 4);
            #pragma unroll
            for (int jp = 0; jp < 2; jp++)
                ldsm_x4(bf[2*jp][0], bf[2*jp][1], bf[2*jp+1][0], bf[2*jp+1][1],
                        bAddr + (uint32_t)(jp * 16 * 36 + k0) * 4);
            #pragma unroll
            for (int i = 0; i < 4; i++)
                #pragma unroll
                for (int j = 0; j < 4; j++)
                    mma_tf32(acc[i][j], af[i], bf[j]);
        }
        __syncthreads();
    }

    #pragma unroll
    for (int i = 0; i < 4; i++) {
        #pragma unroll
        for (int j = 0; j < 4; j++) {
            int r0 = bm + wm + i * 16 + g;
            int r1 = r0 + 8;
            int c0 = bn + wn + j * 8 + 2 * tig;
            float b0 = bias[c0], b1 = bias[c0 + 1];
            float v00 = acc[i][j][0] + b0, v01 = acc[i][j][1] + b1;
            float v10 = acc[i][j][2] + b0, v11 = acc[i][j][3] + b1;
            if (scatter) {
                uint32_t* C = (uint32_t*)Cout;
                int b_0 = r0 >> 11, s_0 = r0 & 2047;
                int b_1 = r1 >> 11, s_1 = r1 & 2047;
                int h = c0 >> 6, dh = c0 & 63;
                size_t i0 = ((((size_t)b_0 * Hv + h) * Sv) + s_0) * DHv + dh;
                size_t i1 = ((((size_t)b_1 * Hv + h) * Sv) + s_1) * DHv + dh;
                C[i0] = f2tf32(v00); C[i0 + 1] = f2tf32(v01);
                C[i1] = f2tf32(v10); C[i1 + 1] = f2tf32(v11);
            } else {
                float* C = (float*)Cout;
                C[(size_t)r0 * Dv + c0] = v00; C[(size_t)r0 * Dv + c0 + 1] = v01;
                C[(size_t)r1 * Dv + c0] = v10; C[(size_t)r1 * Dv + c0 + 1] = v11;
            }
        }
    }
}

__global__ __launch_bounds__(256) void proj_qkv(
    const uint32_t* __restrict__ Aq, const uint32_t* __restrict__ Ak, const uint32_t* __restrict__ Av,
    const uint32_t* __restrict__ Wq, const uint32_t* __restrict__ Wk, const uint32_t* __restrict__ Wv,
    const float* __restrict__ bq, const float* __restrict__ bk, const float* __restrict__ bv,
    uint32_t* __restrict__ Oq, uint32_t* __restrict__ Ok, uint32_t* __restrict__ Ov)
{
    extern __shared__ uint32_t smg[];
    const uint32_t* A = (blockIdx.z == 0) ? Aq : (blockIdx.z == 1) ? Ak : Av;
    const uint32_t* W = (blockIdx.z == 0) ? Wq : (blockIdx.z == 1) ? Wk : Wv;
    const float*    bb = (blockIdx.z == 0) ? bq : (blockIdx.z == 1) ? bk : bv;
    uint32_t*       O = (blockIdx.z == 0) ? Oq : (blockIdx.z == 1) ? Ok : Ov;
    gemm_body(A, W, bb, O, blockIdx.y * 128, blockIdx.x * 128, 1, smg);
}

__global__ __launch_bounds__(256) void gemm_out(
    const uint32_t* __restrict__ A, const uint32_t* __restrict__ W,
    const float* __restrict__ bias, float* __restrict__ C)
{
    extern __shared__ uint32_t smg[];
    gemm_body(A, W, bias, C, blockIdx.y * 128, blockIdx.x * 128, 0, smg);
}

// ---------------- flash attention: Br=256, base-2 softmax, LDSM for Q/K ----------------
__global__ __launch_bounds__(256) void flash_attn(const int* __restrict__ mask)
{
    extern __shared__ uint32_t smf[];
    const int QOFF = 0;
    const int KOFF = 256 * 68;
    const int VOFF = KOFF + 2 * 64 * 68;
    const int TSZ  = 64 * 68;
    const uint32_t smb = (uint32_t)__cvta_generic_to_shared(smf);

    const int qt  = blockIdx.x;
    const int bh  = blockIdx.y;
    const int b   = bh >> 4;
    const int h   = bh & 15;
    const uint32_t* Qg = g_q + (size_t)bh * Sv * DHv + (size_t)qt * 256 * DHv;
    const uint32_t* Kg = g_k + (size_t)bh * Sv * DHv;
    const uint32_t* Vg = g_v + (size_t)bh * Sv * DHv;
    const int* mrow = mask + b * Sv;

    const int tid  = threadIdx.x;
    const int warp = tid >> 5;
    const int lane = tid & 31;
    const int g    = lane >> 2;
    const int tig  = lane & 3;
    const int rw   = warp * 32;

    const int arow  = (lane & 7) + ((lane >> 3) & 1) * 8;
    const int ahalf = (lane >> 4) * 16;
    const int brow  = (lane & 7) + (lane >> 4) * 8;
    const int bhalf = ((lane >> 3) & 1) * 16;

    #pragma unroll
    for (int i = tid; i < 256 * 16; i += 256) {
        int r = i >> 4, c = (i & 15) << 2;
        *(uint4*)&smf[QOFF + r * 68 + c] = *(const uint4*)&Qg[r * 64 + c];
    }

    auto issue_kv = [&](int st, int jt) {
        #pragma unroll
        for (int u = 0; u < 4; u++) {
            int id = tid + u * 256;
            int r = id >> 4, c = (id & 15) << 2;
            cpa16(smb + (uint32_t)(KOFF + st * TSZ + r * 68 + c) * 4,
                  &Kg[(jt * 64 + r) * 64 + c]);
            cpa16(smb + (uint32_t)(VOFF + st * TSZ + r * 68 + c) * 4,
                  &Vg[(jt * 64 + r) * 64 + c]);
        }
        cpa_commit();
    };

    float m_[4], l_[4];
    #pragma unroll
    for (int i = 0; i < 4; i++) { m_[i] = -1e30f; l_[i] = 0.f; }

    float o[2][8][4];
    #pragma unroll
    for (int mb = 0; mb < 2; mb++)
        #pragma unroll
        for (int n = 0; n < 8; n++)
            #pragma unroll
            for (int q = 0; q < 4; q++) o[mb][n][q] = 0.f;

    const float scale2 = 0.0450842298f;   // (1/sqrt(1024)) * log2(e)
    const int srcA = (lane & 28) | (tig >> 1);
    const int srcB = srcA + 2;
    const bool podd = (tig & 1) != 0;

    // lane address bases (Q fixed; K per stage)
    const uint32_t qAddr = smb + (uint32_t)(QOFF + (rw + arow) * 68) * 4 + ahalf;

    issue_kv(0, 0);

    for (int jt = 0; jt < Sv / 64; jt++) {
        asm volatile("cp.async.wait_group 0;" ::: "memory");
        __syncthreads();
        if (jt + 1 < Sv / 64) issue_kv((jt + 1) & 1, jt + 1);

        const uint32_t kAddr = smb + (uint32_t)(KOFF + (jt & 1) * TSZ + brow * 68) * 4 + bhalf;
        const uint32_t* Vs = smf + VOFF + (jt & 1) * TSZ;

        float s[2][8][4];
        #pragma unroll
        for (int mb = 0; mb < 2; mb++)
            #pragma unroll
            for (int n = 0; n < 8; n++)
                #pragma unroll
                for (int q = 0; q < 4; q++) s[mb][n][q] = 0.f;

        #pragma unroll
        for (int k0 = 0; k0 < 64; k0 += 8) {
            uint32_t aq[2][4];
            #pragma unroll
            for (int mb = 0; mb < 2; mb++)
                ldsm_x4(aq[mb][0], aq[mb][1], aq[mb][2], aq[mb][3],
                        qAddr + (uint32_t)(mb * 16 * 68 + k0) * 4);
            uint32_t kf[8][2];
            #pragma unroll
            for (int np = 0; np < 4; np++)
                ldsm_x4(kf[2*np][0], kf[2*np][1], kf[2*np+1][0], kf[2*np+1][1],
                        kAddr + (uint32_t)(np * 16 * 68 + k0) * 4);
            #pragma unroll
            for (int n = 0; n < 8; n++) {
                mma_tf32(s[0][n], aq[0], kf[n]);
                mma_tf32(s[1][n], aq[1], kf[n]);
            }
        }

        float rmax[4];
        #pragma unroll
        for (int i = 0; i < 4; i++) rmax[i] = -1e30f;
        #pragma unroll
        for (int n = 0; n < 8; n++) {
            int c0 = jt * 64 + n * 8 + 2 * tig;
            float msk0 = mrow[c0]     ? 0.f : -1e30f;
            float msk1 = mrow[c0 + 1] ? 0.f : -1e30f;
            #pragma unroll
            for (int mb = 0; mb < 2; mb++) {
                s[mb][n][0] = s[mb][n][0] * scale2 + msk0;
                s[mb][n][1] = s[mb][n][1] * scale2 + msk1;
                s[mb][n][2] = s[mb][n][2] * scale2 + msk0;
                s[mb][n][3] = s[mb][n][3] * scale2 + msk1;
                rmax[mb*2  ] = fmaxf(rmax[mb*2  ], fmaxf(s[mb][n][0], s[mb][n][1]));
                rmax[mb*2+1] = fmaxf(rmax[mb*2+1], fmaxf(s[mb][n][2], s[mb][n][3]));
            }
        }
        #pragma unroll
        for (int i = 0; i < 4; i++) {
            rmax[i] = fmaxf(rmax[i], __shfl_xor_sync(0xffffffffu, rmax[i], 1));
            rmax[i] = fmaxf(rmax[i], __shfl_xor_sync(0xffffffffu, rmax[i], 2));
        }

        float al[4], mn[4];
        #pragma unroll
        for (int i = 0; i < 4; i++) {
            mn[i] = fmaxf(m_[i], rmax[i]);
            al[i] = exp2f(m_[i] - mn[i]);
            m_[i] = mn[i];
        }

        float rs[4] = {0.f, 0.f, 0.f, 0.f};
        #pragma unroll
        for (int n = 0; n < 8; n++) {
            #pragma unroll
            for (int mb = 0; mb < 2; mb++) {
                s[mb][n][0] = exp2f(s[mb][n][0] - mn[mb*2  ]);
                s[mb][n][1] = exp2f(s[mb][n][1] - mn[mb*2  ]);
                s[mb][n][2] = exp2f(s[mb][n][2] - mn[mb*2+1]);
                s[mb][n][3] = exp2f(s[mb][n][3] - mn[mb*2+1]);
                rs[mb*2  ] += s[mb][n][0] + s[mb][n][1];
                rs[mb*2+1] += s[mb][n][2] + s[mb][n][3];
            }
        }
        #pragma unroll
        for (int i = 0; i < 4; i++) {
            rs[i] += __shfl_xor_sync(0xffffffffu, rs[i], 1);
            rs[i] += __shfl_xor_sync(0xffffffffu, rs[i], 2);
            l_[i] = l_[i] * al[i] + rs[i];
        }

        #pragma unroll
        for (int mb = 0; mb < 2; mb++)
            #pragma unroll
            for (int n = 0; n < 8; n++) {
                s[mb][n][0] = __uint_as_float(f2tf32(s[mb][n][0]));
                s[mb][n][1] = __uint_as_float(f2tf32(s[mb][n][1]));
                s[mb][n][2] = __uint_as_float(f2tf32(s[mb][n][2]));
                s[mb][n][3] = __uint_as_float(f2tf32(s[mb][n][3]));
                o[mb][n][0] *= al[mb*2  ];
                o[mb][n][1] *= al[mb*2  ];
                o[mb][n][2] *= al[mb*2+1];
                o[mb][n][3] *= al[mb*2+1];
            }

        #pragma unroll
        for (int k0i = 0; k0i < 8; k0i++) {
            int kr = k0i * 8;
            uint32_t bf[8][2];
            #pragma unroll
            for (int n = 0; n < 8; n++) {
                bf[n][0] = Vs[(kr + tig    ) * 68 + n * 8 + g];
                bf[n][1] = Vs[(kr + tig + 4) * 68 + n * 8 + g];
            }
            #pragma unroll
            for (int mb = 0; mb < 2; mb++) {
                float v00 = __shfl_sync(0xffffffffu, s[mb][k0i][0], srcA);
                float v01 = __shfl_sync(0xffffffffu, s[mb][k0i][1], srcA);
                float v10 = __shfl_sync(0xffffffffu, s[mb][k0i][2], srcA);
                float v11 = __shfl_sync(0xffffffffu, s[mb][k0i][3], srcA);
                float w00 = __shfl_sync(0xffffffffu, s[mb][k0i][0], srcB);
                float w01 = __shfl_sync(0xffffffffu, s[mb][k0i][1], srcB);
                float w10 = __shfl_sync(0xffffffffu, s[mb][k0i][2], srcB);
                float w11 = __shfl_sync(0xffffffffu, s[mb][k0i][3], srcB);
                uint32_t af[4];
                af[0] = __float_as_uint(podd ? v01 : v00);
                af[1] = __float_as_uint(podd ? v11 : v10);
                af[2] = __float_as_uint(podd ? w01 : w00);
                af[3] = __float_as_uint(podd ? w11 : w10);
                #pragma unroll
                for (int n = 0; n < 8; n++)
                    mma_tf32(o[mb][n], af, bf[n]);
            }
        }
    }

    float il[4];
    #pragma unroll
    for (int i = 0; i < 4; i++) il[i] = 1.f / l_[i];

    #pragma unroll
    for (int mb = 0; mb < 2; mb++) {
        int s0 = qt * 256 + rw + mb * 16 + g;
        int s1 = s0 + 8;
        size_t base0 = (((size_t)b * Sv + s0) * Hv + h) * DHv;
        size_t base1 = (((size_t)b * Sv + s1) * Hv + h) * DHv;
        #pragma unroll
        for (int n = 0; n < 8; n++) {
            int dh = n * 8 + 2 * tig;
            g_ctx[base0 + dh    ] = f2tf32(o[mb][n][0] * il[mb*2  ]);
            g_ctx[base0 + dh + 1] = f2tf32(o[mb][n][1] * il[mb*2  ]);
            g_ctx[base1 + dh    ] = f2tf32(o[mb][n][2] * il[mb*2+1]);
            g_ctx[base1 + dh + 1] = f2tf32(o[mb][n][3] * il[mb*2+1]);
        }
    }
}

extern "C" void kernel_launch(void* const* d_in, const int* in_sizes, int n_in,
                              void* d_out, int out_size)
{
    const float* query = (const float*)d_in[0];
    const float* key   = (const float*)d_in[1];
    const float* value = (const float*)d_in[2];
    const int*   mask  = (const int*)  d_in[3];
    const float* Wq    = (const float*)d_in[4];
    const float* bq    = (const float*)d_in[5];
    const float* Wk    = (const float*)d_in[6];
    const float* bk    = (const float*)d_in[7];
    const float* Wv    = (const float*)d_in[8];
    const float* bv    = (const float*)d_in[9];
    const float* Wo    = (const float*)d_in[10];
    const float* bo    = (const float*)d_in[11];
    float* out = (float*)d_out;

    uint32_t *qin, *kin, *vin, *wq, *wk, *wv, *wo, *gq, *gk, *gv, *gctx;
    cudaGetSymbolAddress((void**)&qin,  g_qin);
    cudaGetSymbolAddress((void**)&kin,  g_kin);
    cudaGetSymbolAddress((void**)&vin,  g_vin);
    cudaGetSymbolAddress((void**)&wq,   g_wq);
    cudaGetSymbolAddress((void**)&wk,   g_wk);
    cudaGetSymbolAddress((void**)&wv,   g_wv);
    cudaGetSymbolAddress((void**)&wo,   g_wo);
    cudaGetSymbolAddress((void**)&gq,   g_q);
    cudaGetSymbolAddress((void**)&gk,   g_k);
    cudaGetSymbolAddress((void**)&gv,   g_v);
    cudaGetSymbolAddress((void**)&gctx, g_ctx);

    const int smem_gemm = 6 * 128 * 36 * 4;              // 110592 (2 CTAs/SM)
    const int smem_attn = (256 * 68 + 4 * 64 * 68) * 4;  // 139264
    cudaFuncSetAttribute(proj_qkv,   cudaFuncAttributeMaxDynamicSharedMemorySize, smem_gemm);
    cudaFuncSetAttribute(gemm_out,   cudaFuncAttributeMaxDynamicSharedMemorySize, smem_gemm);
    cudaFuncSetAttribute(flash_attn, cudaFuncAttributeMaxDynamicSharedMemorySize, smem_attn);

    const int NIN4 = Mv * Dv / 4;
    const int NW4  = Dv * Dv / 4;
    cvt3_kernel<<<dim3(1024, 3), 256>>>((const float4*)query, (const float4*)key, (const float4*)value,
                                        (uint4*)qin, (uint4*)kin, (uint4*)vin, NIN4);
    cvt4_kernel<<<dim3(256, 4), 256>>>((const float4*)Wq, (const float4*)Wk, (const float4*)Wv, (const float4*)Wo,
                                       (uint4*)wq, (uint4*)wk, (uint4*)wv, (uint4*)wo, NW4);

    proj_qkv<<<dim3(Dv / 128, Mv / 128, 3), 256, smem_gemm>>>(
        qin, kin, vin, wq, wk, wv, bq, bk, bv, gq, gk, gv);

    flash_attn<<<dim3(Sv / 256, Bv * Hv), 256, smem_attn>>>(mask);

    gemm_out<<<dim3(Dv / 128, Mv / 128), 256, smem_gemm>>>(gctx, wo, bo, out);
}

// round 15
// speedup vs baseline: 1.6550x; 1.5545x over previous
#include <cuda_runtime.h>
#include <cstdint>

#define Bv 4
#define Sv 2048
#define Dv 1024
#define Hv 16
#define DHv 64
#define Mv (Bv*Sv)          // 8192

// Scratch: fp16 everywhere
__device__ uint16_t g_qin[Mv*Dv];
__device__ uint16_t g_kin[Mv*Dv];
__device__ uint16_t g_vin[Mv*Dv];
__device__ uint16_t g_wq[Dv*Dv];
__device__ uint16_t g_wk[Dv*Dv];
__device__ uint16_t g_wv[Dv*Dv];
__device__ uint16_t g_wo[Dv*Dv];
__device__ uint16_t g_q[Mv*Dv];    // [b,h,s,dh]
__device__ uint16_t g_k[Mv*Dv];
__device__ uint16_t g_v[Mv*Dv];
__device__ uint16_t g_ctx[Mv*Dv];  // [b,s,h,dh]

__device__ __forceinline__ uint32_t pack_f16x2(float hi, float lo) {
    uint32_t r;
    asm("cvt.rn.f16x2.f32 %0, %1, %2;" : "=r"(r) : "f"(hi), "f"(lo));
    return r;
}

__device__ __forceinline__ void mma_f16(float c[4], const uint32_t a[4], const uint32_t b[2]) {
    asm volatile(
        "mma.sync.aligned.m16n8k16.row.col.f32.f16.f16.f32 "
        "{%0,%1,%2,%3}, {%4,%5,%6,%7}, {%8,%9}, {%0,%1,%2,%3};\n"
        : "+f"(c[0]), "+f"(c[1]), "+f"(c[2]), "+f"(c[3])
        : "r"(a[0]), "r"(a[1]), "r"(a[2]), "r"(a[3]), "r"(b[0]), "r"(b[1]));
}

__device__ __forceinline__ void ldsm_x4(uint32_t& r0, uint32_t& r1, uint32_t& r2, uint32_t& r3,
                                        uint32_t addr) {
    asm volatile("ldmatrix.sync.aligned.m8n8.x4.shared.b16 {%0,%1,%2,%3}, [%4];"
        : "=r"(r0), "=r"(r1), "=r"(r2), "=r"(r3) : "r"(addr));
}
__device__ __forceinline__ void ldsm_x4t(uint32_t& r0, uint32_t& r1, uint32_t& r2, uint32_t& r3,
                                         uint32_t addr) {
    asm volatile("ldmatrix.sync.aligned.m8n8.x4.trans.shared.b16 {%0,%1,%2,%3}, [%4];"
        : "=r"(r0), "=r"(r1), "=r"(r2), "=r"(r3) : "r"(addr));
}

__device__ __forceinline__ void cpa16(uint32_t saddr, const void* gptr) {
    asm volatile("cp.async.cg.shared.global [%0], [%1], 16;" :: "r"(saddr), "l"(gptr));
}
__device__ __forceinline__ void cpa_commit() {
    asm volatile("cp.async.commit_group;" ::: "memory");
}

// ---------------- conversions: fp32 -> fp16 ----------------

__global__ __launch_bounds__(256) void cvt3_kernel(
    const float4* __restrict__ a, const float4* __restrict__ b, const float4* __restrict__ c,
    uint2* __restrict__ oa, uint2* __restrict__ ob, uint2* __restrict__ oc, int n4)
{
    const float4* in  = (blockIdx.y == 0) ? a  : (blockIdx.y == 1) ? b  : c;
    uint2*        out = (blockIdx.y == 0) ? oa : (blockIdx.y == 1) ? ob : oc;
    int i = blockIdx.x * blockDim.x + threadIdx.x;
    int stride = gridDim.x * blockDim.x;
    for (; i < n4; i += stride) {
        float4 v = in[i];
        out[i] = make_uint2(pack_f16x2(v.y, v.x), pack_f16x2(v.w, v.z));
    }
}

__global__ __launch_bounds__(256) void cvt4_kernel(
    const float4* __restrict__ a, const float4* __restrict__ b,
    const float4* __restrict__ c, const float4* __restrict__ d,
    uint2* __restrict__ oa, uint2* __restrict__ ob,
    uint2* __restrict__ oc, uint2* __restrict__ od, int n4)
{
    const float4* in  = (blockIdx.y == 0) ? a  : (blockIdx.y == 1) ? b  : (blockIdx.y == 2) ? c  : d;
    uint2*        out = (blockIdx.y == 0) ? oa : (blockIdx.y == 1) ? ob : (blockIdx.y == 2) ? oc : od;
    int i = blockIdx.x * blockDim.x + threadIdx.x;
    int stride = gridDim.x * blockDim.x;
    for (; i < n4; i += stride) {
        float4 v = in[i];
        out[i] = make_uint2(pack_f16x2(v.y, v.x), pack_f16x2(v.w, v.z));
    }
}

// ---------------- GEMM fp16: 128x128 tile, warp 64x32, m16n8k16, 3-stage cp.async ----------------
// Stage: A[128 rows][32 halves, row stride 80B] + B same. Stage = 20480B, 3 stages = 61440B.

__device__ __forceinline__ void gemm_body(
    const uint16_t* __restrict__ A, const uint16_t* __restrict__ W,
    const float* __restrict__ bias, void* __restrict__ Cout,
    int bm, int bn, int scatter, uint8_t* smg)
{
    const uint32_t smb = (uint32_t)__cvta_generic_to_shared(smg);

    const int tid  = threadIdx.x;
    const int warp = tid >> 5;
    const int lane = tid & 31;
    const int wm   = (warp >> 2) * 64;
    const int wn   = (warp & 3) * 32;
    const int g    = lane >> 2;
    const int tig  = lane & 3;
    const int lrow = lane & 15;
    const int lhalf = (lane >> 4) << 4;   // bytes

    float acc[4][4][4];
    #pragma unroll
    for (int i = 0; i < 4; i++)
        #pragma unroll
        for (int j = 0; j < 4; j++)
            #pragma unroll
            for (int t = 0; t < 4; t++) acc[i][j][t] = 0.f;

    auto issue = [&](int st, int kt) {
        uint32_t base = smb + (uint32_t)st * 20480u;
        #pragma unroll
        for (int u = 0; u < 2; u++) {
            int id = tid + u * 256;          // 0..511
            int r = id >> 2, c = id & 3;
            cpa16(base + (uint32_t)(r * 80 + c * 16),
                  &A[(size_t)(bm + r) * Dv + kt + c * 8]);
        }
        #pragma unroll
        for (int u = 0; u < 2; u++) {
            int id = tid + u * 256;
            int r = id >> 2, c = id & 3;
            cpa16(base + 10240u + (uint32_t)(r * 80 + c * 16),
                  &W[(size_t)(bn + r) * Dv + kt + c * 8]);
        }
        cpa_commit();
    };

    issue(0, 0);
    issue(1, 32);

    for (int t = 0; t < 32; t++) {
        if (t == 31) asm volatile("cp.async.wait_group 0;" ::: "memory");
        else         asm volatile("cp.async.wait_group 1;" ::: "memory");
        __syncthreads();
        if (t + 2 < 32) issue((t + 2) % 3, (t + 2) * 32);

        const uint32_t stBase = smb + (uint32_t)((t % 3) * 20480);
        const uint32_t aAddr = stBase + (uint32_t)((wm + lrow) * 80) + lhalf;
        const uint32_t bAddr = stBase + 10240u + (uint32_t)((wn + lrow) * 80) + lhalf;

        #pragma unroll
        for (int kc = 0; kc < 2; kc++) {
            uint32_t af[4][4], bf[4][2];
            #pragma unroll
            for (int i = 0; i < 4; i++)
                ldsm_x4(af[i][0], af[i][1], af[i][2], af[i][3],
                        aAddr + (uint32_t)(i * 1280 + kc * 32));
            #pragma unroll
            for (int jp = 0; jp < 2; jp++)
                ldsm_x4(bf[2*jp][0], bf[2*jp+1][0], bf[2*jp][1], bf[2*jp+1][1],
                        bAddr + (uint32_t)(jp * 1280 + kc * 32));
            #pragma unroll
            for (int i = 0; i < 4; i++)
                #pragma unroll
                for (int j = 0; j < 4; j++)
                    mma_f16(acc[i][j], af[i], bf[j]);
        }
        __syncthreads();
    }

    #pragma unroll
    for (int i = 0; i < 4; i++) {
        #pragma unroll
        for (int j = 0; j < 4; j++) {
            int r0 = bm + wm + i * 16 + g;
            int r1 = r0 + 8;
            int c0 = bn + wn + j * 8 + 2 * tig;
            float b0 = bias[c0], b1 = bias[c0 + 1];
            float v00 = acc[i][j][0] + b0, v01 = acc[i][j][1] + b1;
            float v10 = acc[i][j][2] + b0, v11 = acc[i][j][3] + b1;
            if (scatter) {
                uint16_t* C = (uint16_t*)Cout;
                int b_0 = r0 >> 11, s_0 = r0 & 2047;
                int b_1 = r1 >> 11, s_1 = r1 & 2047;
                int h = c0 >> 6, dh = c0 & 63;
                size_t i0 = ((((size_t)b_0 * Hv + h) * Sv) + s_0) * DHv + dh;
                size_t i1 = ((((size_t)b_1 * Hv + h) * Sv) + s_1) * DHv + dh;
                *(uint32_t*)&C[i0] = pack_f16x2(v01, v00);
                *(uint32_t*)&C[i1] = pack_f16x2(v11, v10);
            } else {
                float* C = (float*)Cout;
                C[(size_t)r0 * Dv + c0] = v00; C[(size_t)r0 * Dv + c0 + 1] = v01;
                C[(size_t)r1 * Dv + c0] = v10; C[(size_t)r1 * Dv + c0 + 1] = v11;
            }
        }
    }
}

__global__ __launch_bounds__(256) void proj_qkv(
    const uint16_t* __restrict__ Aq, const uint16_t* __restrict__ Ak, const uint16_t* __restrict__ Av,
    const uint16_t* __restrict__ Wq, const uint16_t* __restrict__ Wk, const uint16_t* __restrict__ Wv,
    const float* __restrict__ bq, const float* __restrict__ bk, const float* __restrict__ bv,
    uint16_t* __restrict__ Oq, uint16_t* __restrict__ Ok, uint16_t* __restrict__ Ov)
{
    extern __shared__ uint8_t smg[];
    const uint16_t* A = (blockIdx.z == 0) ? Aq : (blockIdx.z == 1) ? Ak : Av;
    const uint16_t* W = (blockIdx.z == 0) ? Wq : (blockIdx.z == 1) ? Wk : Wv;
    const float*    bb = (blockIdx.z == 0) ? bq : (blockIdx.z == 1) ? bk : bv;
    uint16_t*       O = (blockIdx.z == 0) ? Oq : (blockIdx.z == 1) ? Ok : Ov;
    gemm_body(A, W, bb, O, blockIdx.y * 128, blockIdx.x * 128, 1, smg);
}

__global__ __launch_bounds__(256) void gemm_out(
    const uint16_t* __restrict__ A, const uint16_t* __restrict__ W,
    const float* __restrict__ bias, float* __restrict__ C)
{
    extern __shared__ uint8_t smg[];
    gemm_body(A, W, bias, C, blockIdx.y * 128, blockIdx.x * 128, 0, smg);
}

// ---------------- flash attention fp16: Br=256 (8 warps x 32 rows), Bc=64 ----------------
// smem bytes: Q at 0 (256 rows x 144B = 36864), K at 36864 (2 x 64 x 144 = 18432),
// V at 55296 (18432). Total 73728.
#define QB 0
#define KB 36864
#define VB 55296
#define FLASH_SMEM 73728

__global__ __launch_bounds__(256) void flash_attn(const int* __restrict__ mask)
{
    extern __shared__ uint8_t smf[];
    const uint32_t smb = (uint32_t)__cvta_generic_to_shared(smf);

    const int qt  = blockIdx.x;
    const int bh  = blockIdx.y;
    const int b   = bh >> 4;
    const int h   = bh & 15;
    const uint16_t* Qg = g_q + (size_t)bh * Sv * DHv + (size_t)qt * 256 * DHv;
    const uint16_t* Kg = g_k + (size_t)bh * Sv * DHv;
    const uint16_t* Vg = g_v + (size_t)bh * Sv * DHv;
    const int* mrow = mask + b * Sv;

    const int tid  = threadIdx.x;
    const int warp = tid >> 5;
    const int lane = tid & 31;
    const int g    = lane >> 2;
    const int tig  = lane & 3;
    const int rw   = warp * 32;
    const int lrow = lane & 15;
    const int lhalf = (lane >> 4) << 4;   // bytes

    // stage Q (256 x 64 halves -> rows padded to 144B)
    #pragma unroll
    for (int i = tid; i < 2048; i += 256) {
        int r = i >> 3, c = i & 7;
        *(uint4*)(smf + QB + r * 144 + c * 16) = *(const uint4*)&Qg[r * 64 + c * 8];
    }

    auto issue_kv = [&](int st, int jt) {
        #pragma unroll
        for (int u = 0; u < 2; u++) {
            int id = tid + u * 256;          // K: 0..511
            int r = id >> 3, c = id & 7;
            cpa16(smb + KB + (uint32_t)(st * 9216 + r * 144 + c * 16),
                  &Kg[(jt * 64 + r) * 64 + c * 8]);
        }
        #pragma unroll
        for (int u = 0; u < 2; u++) {
            int id = tid + u * 256;          // V
            int r = id >> 3, c = id & 7;
            cpa16(smb + VB + (uint32_t)(st * 9216 + r * 144 + c * 16),
                  &Vg[(jt * 64 + r) * 64 + c * 8]);
        }
        cpa_commit();
    };

    float m_[4], l_[4];
    #pragma unroll
    for (int i = 0; i < 4; i++) { m_[i] = -1e30f; l_[i] = 0.f; }

    float o[2][8][4];
    #pragma unroll
    for (int mb = 0; mb < 2; mb++)
        #pragma unroll
        for (int n = 0; n < 8; n++)
            #pragma unroll
            for (int q = 0; q < 4; q++) o[mb][n][q] = 0.f;

    const float scale2 = 0.0450842298f;   // (1/sqrt(1024)) * log2(e)
    const uint32_t qAddr = smb + QB + (uint32_t)((rw + lrow) * 144) + lhalf;

    issue_kv(0, 0);

    for (int jt = 0; jt < Sv / 64; jt++) {
        asm volatile("cp.async.wait_group 0;" ::: "memory");
        __syncthreads();
        if (jt + 1 < Sv / 64) issue_kv((jt + 1) & 1, jt + 1);

        const uint32_t kAddr = smb + KB + (uint32_t)((jt & 1) * 9216 + lrow * 144) + lhalf;
        const uint32_t vAddr = smb + VB + (uint32_t)((jt & 1) * 9216 + lrow * 144) + lhalf;

        // ---- S = Q @ K^T : m16n8k16, dh = 4 chunks of 16 ----
        float s[2][8][4];
        #pragma unroll
        for (int mb = 0; mb < 2; mb++)
            #pragma unroll
            for (int n = 0; n < 8; n++)
                #pragma unroll
                for (int q = 0; q < 4; q++) s[mb][n][q] = 0.f;

        #pragma unroll
        for (int kc = 0; kc < 4; kc++) {
            uint32_t aq[2][4];
            #pragma unroll
            for (int mb = 0; mb < 2; mb++)
                ldsm_x4(aq[mb][0], aq[mb][1], aq[mb][2], aq[mb][3],
                        qAddr + (uint32_t)(mb * 2304 + kc * 32));
            uint32_t kf[8][2];
            #pragma unroll
            for (int np = 0; np < 4; np++)
                ldsm_x4(kf[2*np][0], kf[2*np+1][0], kf[2*np][1], kf[2*np+1][1],
                        kAddr + (uint32_t)(np * 2304 + kc * 32));
            #pragma unroll
            for (int n = 0; n < 8; n++) {
                mma_f16(s[0][n], aq[0], kf[n]);
                mma_f16(s[1][n], aq[1], kf[n]);
            }
        }

        // ---- mask + scale + rowmax ----
        float rmax[4];
        #pragma unroll
        for (int i = 0; i < 4; i++) rmax[i] = -1e30f;
        #pragma unroll
        for (int n = 0; n < 8; n++) {
            int c0 = jt * 64 + n * 8 + 2 * tig;
            float msk0 = mrow[c0]     ? 0.f : -1e30f;
            float msk1 = mrow[c0 + 1] ? 0.f : -1e30f;
            #pragma unroll
            for (int mb = 0; mb < 2; mb++) {
                s[mb][n][0] = s[mb][n][0] * scale2 + msk0;
                s[mb][n][1] = s[mb][n][1] * scale2 + msk1;
                s[mb][n][2] = s[mb][n][2] * scale2 + msk0;
                s[mb][n][3] = s[mb][n][3] * scale2 + msk1;
                rmax[mb*2  ] = fmaxf(rmax[mb*2  ], fmaxf(s[mb][n][0], s[mb][n][1]));
                rmax[mb*2+1] = fmaxf(rmax[mb*2+1], fmaxf(s[mb][n][2], s[mb][n][3]));
            }
        }
        #pragma unroll
        for (int i = 0; i < 4; i++) {
            rmax[i] = fmaxf(rmax[i], __shfl_xor_sync(0xffffffffu, rmax[i], 1));
            rmax[i] = fmaxf(rmax[i], __shfl_xor_sync(0xffffffffu, rmax[i], 2));
        }

        float al[4], mn[4];
        #pragma unroll
        for (int i = 0; i < 4; i++) {
            mn[i] = fmaxf(m_[i], rmax[i]);
            al[i] = exp2f(m_[i] - mn[i]);
            m_[i] = mn[i];
        }

        float rs[4] = {0.f, 0.f, 0.f, 0.f};
        #pragma unroll
        for (int n = 0; n < 8; n++) {
            #pragma unroll
            for (int mb = 0; mb < 2; mb++) {
                s[mb][n][0] = exp2f(s[mb][n][0] - mn[mb*2  ]);
                s[mb][n][1] = exp2f(s[mb][n][1] - mn[mb*2  ]);
                s[mb][n][2] = exp2f(s[mb][n][2] - mn[mb*2+1]);
                s[mb][n][3] = exp2f(s[mb][n][3] - mn[mb*2+1]);
                rs[mb*2  ] += s[mb][n][0] + s[mb][n][1];
                rs[mb*2+1] += s[mb][n][2] + s[mb][n][3];
            }
        }
        #pragma unroll
        for (int i = 0; i < 4; i++) {
            rs[i] += __shfl_xor_sync(0xffffffffu, rs[i], 1);
            rs[i] += __shfl_xor_sync(0xffffffffu, rs[i], 2);
            l_[i] = l_[i] * al[i] + rs[i];
        }

        // rescale O
        #pragma unroll
        for (int mb = 0; mb < 2; mb++)
            #pragma unroll
            for (int n = 0; n < 8; n++) {
                o[mb][n][0] *= al[mb*2  ];
                o[mb][n][1] *= al[mb*2  ];
                o[mb][n][2] *= al[mb*2+1];
                o[mb][n][3] *= al[mb*2+1];
            }

        // ---- O += P @ V : P packed from registers, V via ldmatrix.trans ----
        #pragma unroll
        for (int c = 0; c < 4; c++) {
            uint32_t vf[8][2];
            #pragma unroll
            for (int jp = 0; jp < 4; jp++)
                ldsm_x4t(vf[2*jp][0], vf[2*jp][1], vf[2*jp+1][0], vf[2*jp+1][1],
                         vAddr + (uint32_t)(c * 2304 + jp * 32));
            #pragma unroll
            for (int mb = 0; mb < 2; mb++) {
                uint32_t a[4];
                a[0] = pack_f16x2(s[mb][2*c  ][1], s[mb][2*c  ][0]);
                a[1] = pack_f16x2(s[mb][2*c  ][3], s[mb][2*c  ][2]);
                a[2] = pack_f16x2(s[mb][2*c+1][1], s[mb][2*c+1][0]);
                a[3] = pack_f16x2(s[mb][2*c+1][3], s[mb][2*c+1][2]);
                #pragma unroll
                for (int n = 0; n < 8; n++)
                    mma_f16(o[mb][n], a, vf[n]);
            }
        }
    }

    float il[4];
    #pragma unroll
    for (int i = 0; i < 4; i++) il[i] = 1.f / l_[i];

    #pragma unroll
    for (int mb = 0; mb < 2; mb++) {
        int s0 = qt * 256 + rw + mb * 16 + g;
        int s1 = s0 + 8;
        size_t base0 = (((size_t)b * Sv + s0) * Hv + h) * DHv;
        size_t base1 = (((size_t)b * Sv + s1) * Hv + h) * DHv;
        #pragma unroll
        for (int n = 0; n < 8; n++) {
            int dh = n * 8 + 2 * tig;
            *(uint32_t*)&g_ctx[base0 + dh] = pack_f16x2(o[mb][n][1] * il[mb*2  ], o[mb][n][0] * il[mb*2  ]);
            *(uint32_t*)&g_ctx[base1 + dh] = pack_f16x2(o[mb][n][3] * il[mb*2+1], o[mb][n][2] * il[mb*2+1]);
        }
    }
}

extern "C" void kernel_launch(void* const* d_in, const int* in_sizes, int n_in,
                              void* d_out, int out_size)
{
    const float* query = (const float*)d_in[0];
    const float* key   = (const float*)d_in[1];
    const float* value = (const float*)d_in[2];
    const int*   mask  = (const int*)  d_in[3];
    const float* Wq    = (const float*)d_in[4];
    const float* bq    = (const float*)d_in[5];
    const float* Wk    = (const float*)d_in[6];
    const float* bk    = (const float*)d_in[7];
    const float* Wv    = (const float*)d_in[8];
    const float* bv    = (const float*)d_in[9];
    const float* Wo    = (const float*)d_in[10];
    const float* bo    = (const float*)d_in[11];
    float* out = (float*)d_out;

    uint16_t *qin, *kin, *vin, *wq, *wk, *wv, *wo, *gq, *gk, *gv, *gctx;
    cudaGetSymbolAddress((void**)&qin,  g_qin);
    cudaGetSymbolAddress((void**)&kin,  g_kin);
    cudaGetSymbolAddress((void**)&vin,  g_vin);
    cudaGetSymbolAddress((void**)&wq,   g_wq);
    cudaGetSymbolAddress((void**)&wk,   g_wk);
    cudaGetSymbolAddress((void**)&wv,   g_wv);
    cudaGetSymbolAddress((void**)&wo,   g_wo);
    cudaGetSymbolAddress((void**)&gq,   g_q);
    cudaGetSymbolAddress((void**)&gk,   g_k);
    cudaGetSymbolAddress((void**)&gv,   g_v);
    cudaGetSymbolAddress((void**)&gctx, g_ctx);

    const int smem_gemm = 61440;
    const int smem_attn = FLASH_SMEM;    // 73728
    cudaFuncSetAttribute(proj_qkv,   cudaFuncAttributeMaxDynamicSharedMemorySize, smem_gemm);
    cudaFuncSetAttribute(gemm_out,   cudaFuncAttributeMaxDynamicSharedMemorySize, smem_gemm);
    cudaFuncSetAttribute(flash_attn, cudaFuncAttributeMaxDynamicSharedMemorySize, smem_attn);

    const int NIN4 = Mv * Dv / 4;
    const int NW4  = Dv * Dv / 4;
    cvt3_kernel<<<dim3(1024, 3), 256>>>((const float4*)query, (const float4*)key, (const float4*)value,
                                        (uint2*)qin, (uint2*)kin, (uint2*)vin, NIN4);
    cvt4_kernel<<<dim3(256, 4), 256>>>((const float4*)Wq, (const float4*)Wk, (const float4*)Wv, (const float4*)Wo,
                                       (uint2*)wq, (uint2*)wk, (uint2*)wv, (uint2*)wo, NW4);

    proj_qkv<<<dim3(Dv / 128, Mv / 128, 3), 256, smem_gemm>>>(
        qin, kin, vin, wq, wk, wv, bq, bk, bv, gq, gk, gv);

    flash_attn<<<dim3(Sv / 256, Bv * Hv), 256, smem_attn>>>(mask);

    gemm_out<<<dim3(Dv / 128, Mv / 128), 256, smem_gemm>>>(gctx, wo, bo, out);
}

// round 16
// speedup vs baseline: 1.8608x; 1.1244x over previous
#include <cuda_runtime.h>
#include <cstdint>

#define Bv 4
#define Sv 2048
#define Dv 1024
#define Hv 16
#define DHv 64
#define Mv (Bv*Sv)          // 8192

// Scratch: fp16 everywhere
__device__ uint16_t g_qin[Mv*Dv];
__device__ uint16_t g_kin[Mv*Dv];
__device__ uint16_t g_vin[Mv*Dv];
__device__ uint16_t g_wq[Dv*Dv];
__device__ uint16_t g_wk[Dv*Dv];
__device__ uint16_t g_wv[Dv*Dv];
__device__ uint16_t g_wo[Dv*Dv];
__device__ uint16_t g_q[Mv*Dv];    // [b,h,s,dh]
__device__ uint16_t g_k[Mv*Dv];
__device__ uint16_t g_v[Mv*Dv];
__device__ uint16_t g_ctx[Mv*Dv];  // [b,s,h,dh]

__device__ __forceinline__ uint32_t pack_f16x2(float hi, float lo) {
    uint32_t r;
    asm("cvt.rn.f16x2.f32 %0, %1, %2;" : "=r"(r) : "f"(hi), "f"(lo));
    return r;
}

__device__ __forceinline__ void mma_f16(float c[4], const uint32_t a[4], const uint32_t b[2]) {
    asm volatile(
        "mma.sync.aligned.m16n8k16.row.col.f32.f16.f16.f32 "
        "{%0,%1,%2,%3}, {%4,%5,%6,%7}, {%8,%9}, {%0,%1,%2,%3};\n"
        : "+f"(c[0]), "+f"(c[1]), "+f"(c[2]), "+f"(c[3])
        : "r"(a[0]), "r"(a[1]), "r"(a[2]), "r"(a[3]), "r"(b[0]), "r"(b[1]));
}

__device__ __forceinline__ void ldsm_x4(uint32_t& r0, uint32_t& r1, uint32_t& r2, uint32_t& r3,
                                        uint32_t addr) {
    asm volatile("ldmatrix.sync.aligned.m8n8.x4.shared.b16 {%0,%1,%2,%3}, [%4];"
        : "=r"(r0), "=r"(r1), "=r"(r2), "=r"(r3) : "r"(addr));
}
__device__ __forceinline__ void ldsm_x4t(uint32_t& r0, uint32_t& r1, uint32_t& r2, uint32_t& r3,
                                         uint32_t addr) {
    asm volatile("ldmatrix.sync.aligned.m8n8.x4.trans.shared.b16 {%0,%1,%2,%3}, [%4];"
        : "=r"(r0), "=r"(r1), "=r"(r2), "=r"(r3) : "r"(addr));
}

__device__ __forceinline__ void cpa16(uint32_t saddr, const void* gptr) {
    asm volatile("cp.async.cg.shared.global [%0], [%1], 16;" :: "r"(saddr), "l"(gptr));
}
__device__ __forceinline__ void cpa_commit() {
    asm volatile("cp.async.commit_group;" ::: "memory");
}

// ---------------- conversions: fp32 -> fp16 ----------------

__global__ __launch_bounds__(256) void cvt3_kernel(
    const float4* __restrict__ a, const float4* __restrict__ b, const float4* __restrict__ c,
    uint2* __restrict__ oa, uint2* __restrict__ ob, uint2* __restrict__ oc, int n4)
{
    const float4* in  = (blockIdx.y == 0) ? a  : (blockIdx.y == 1) ? b  : c;
    uint2*        out = (blockIdx.y == 0) ? oa : (blockIdx.y == 1) ? ob : oc;
    int i = blockIdx.x * blockDim.x + threadIdx.x;
    int stride = gridDim.x * blockDim.x;
    for (; i < n4; i += stride) {
        float4 v = in[i];
        out[i] = make_uint2(pack_f16x2(v.y, v.x), pack_f16x2(v.w, v.z));
    }
}

__global__ __launch_bounds__(256) void cvt4_kernel(
    const float4* __restrict__ a, const float4* __restrict__ b,
    const float4* __restrict__ c, const float4* __restrict__ d,
    uint2* __restrict__ oa, uint2* __restrict__ ob,
    uint2* __restrict__ oc, uint2* __restrict__ od, int n4)
{
    const float4* in  = (blockIdx.y == 0) ? a  : (blockIdx.y == 1) ? b  : (blockIdx.y == 2) ? c  : d;
    uint2*        out = (blockIdx.y == 0) ? oa : (blockIdx.y == 1) ? ob : (blockIdx.y == 2) ? oc : od;
    int i = blockIdx.x * blockDim.x + threadIdx.x;
    int stride = gridDim.x * blockDim.x;
    for (; i < n4; i += stride) {
        float4 v = in[i];
        out[i] = make_uint2(pack_f16x2(v.y, v.x), pack_f16x2(v.w, v.z));
    }
}

// ---------------- GEMM fp16 (R15-proven, unchanged): 128x128 tile, warp 64x32 ----------------

__device__ __forceinline__ void gemm_body(
    const uint16_t* __restrict__ A, const uint16_t* __restrict__ W,
    const float* __restrict__ bias, void* __restrict__ Cout,
    int bm, int bn, int scatter, uint8_t* smg)
{
    const uint32_t smb = (uint32_t)__cvta_generic_to_shared(smg);

    const int tid  = threadIdx.x;
    const int warp = tid >> 5;
    const int lane = tid & 31;
    const int wm   = (warp >> 2) * 64;
    const int wn   = (warp & 3) * 32;
    const int g    = lane >> 2;
    const int tig  = lane & 3;
    const int lrow = lane & 15;
    const int lhalf = (lane >> 4) << 4;   // bytes

    float acc[4][4][4];
    #pragma unroll
    for (int i = 0; i < 4; i++)
        #pragma unroll
        for (int j = 0; j < 4; j++)
            #pragma unroll
            for (int t = 0; t < 4; t++) acc[i][j][t] = 0.f;

    auto issue = [&](int st, int kt) {
        uint32_t base = smb + (uint32_t)st * 20480u;
        #pragma unroll
        for (int u = 0; u < 2; u++) {
            int id = tid + u * 256;
            int r = id >> 2, c = id & 3;
            cpa16(base + (uint32_t)(r * 80 + c * 16),
                  &A[(size_t)(bm + r) * Dv + kt + c * 8]);
        }
        #pragma unroll
        for (int u = 0; u < 2; u++) {
            int id = tid + u * 256;
            int r = id >> 2, c = id & 3;
            cpa16(base + 10240u + (uint32_t)(r * 80 + c * 16),
                  &W[(size_t)(bn + r) * Dv + kt + c * 8]);
        }
        cpa_commit();
    };

    issue(0, 0);
    issue(1, 32);

    for (int t = 0; t < 32; t++) {
        if (t == 31) asm volatile("cp.async.wait_group 0;" ::: "memory");
        else         asm volatile("cp.async.wait_group 1;" ::: "memory");
        __syncthreads();
        if (t + 2 < 32) issue((t + 2) % 3, (t + 2) * 32);

        const uint32_t stBase = smb + (uint32_t)((t % 3) * 20480);
        const uint32_t aAddr = stBase + (uint32_t)((wm + lrow) * 80) + lhalf;
        const uint32_t bAddr = stBase + 10240u + (uint32_t)((wn + lrow) * 80) + lhalf;

        #pragma unroll
        for (int kc = 0; kc < 2; kc++) {
            uint32_t af[4][4], bf[4][2];
            #pragma unroll
            for (int i = 0; i < 4; i++)
                ldsm_x4(af[i][0], af[i][1], af[i][2], af[i][3],
                        aAddr + (uint32_t)(i * 1280 + kc * 32));
            #pragma unroll
            for (int jp = 0; jp < 2; jp++)
                ldsm_x4(bf[2*jp][0], bf[2*jp+1][0], bf[2*jp][1], bf[2*jp+1][1],
                        bAddr + (uint32_t)(jp * 1280 + kc * 32));
            #pragma unroll
            for (int i = 0; i < 4; i++)
                #pragma unroll
                for (int j = 0; j < 4; j++)
                    mma_f16(acc[i][j], af[i], bf[j]);
        }
        __syncthreads();
    }

    #pragma unroll
    for (int i = 0; i < 4; i++) {
        #pragma unroll
        for (int j = 0; j < 4; j++) {
            int r0 = bm + wm + i * 16 + g;
            int r1 = r0 + 8;
            int c0 = bn + wn + j * 8 + 2 * tig;
            float b0 = bias[c0], b1 = bias[c0 + 1];
            float v00 = acc[i][j][0] + b0, v01 = acc[i][j][1] + b1;
            float v10 = acc[i][j][2] + b0, v11 = acc[i][j][3] + b1;
            if (scatter) {
                uint16_t* C = (uint16_t*)Cout;
                int b_0 = r0 >> 11, s_0 = r0 & 2047;
                int b_1 = r1 >> 11, s_1 = r1 & 2047;
                int h = c0 >> 6, dh = c0 & 63;
                size_t i0 = ((((size_t)b_0 * Hv + h) * Sv) + s_0) * DHv + dh;
                size_t i1 = ((((size_t)b_1 * Hv + h) * Sv) + s_1) * DHv + dh;
                *(uint32_t*)&C[i0] = pack_f16x2(v01, v00);
                *(uint32_t*)&C[i1] = pack_f16x2(v11, v10);
            } else {
                float* C = (float*)Cout;
                C[(size_t)r0 * Dv + c0] = v00; C[(size_t)r0 * Dv + c0 + 1] = v01;
                C[(size_t)r1 * Dv + c0] = v10; C[(size_t)r1 * Dv + c0 + 1] = v11;
            }
        }
    }
}

__global__ __launch_bounds__(256) void proj_qkv(
    const uint16_t* __restrict__ Aq, const uint16_t* __restrict__ Ak, const uint16_t* __restrict__ Av,
    const uint16_t* __restrict__ Wq, const uint16_t* __restrict__ Wk, const uint16_t* __restrict__ Wv,
    const float* __restrict__ bq, const float* __restrict__ bk, const float* __restrict__ bv,
    uint16_t* __restrict__ Oq, uint16_t* __restrict__ Ok, uint16_t* __restrict__ Ov)
{
    extern __shared__ uint8_t smg[];
    const uint16_t* A = (blockIdx.z == 0) ? Aq : (blockIdx.z == 1) ? Ak : Av;
    const uint16_t* W = (blockIdx.z == 0) ? Wq : (blockIdx.z == 1) ? Wk : Wv;
    const float*    bb = (blockIdx.z == 0) ? bq : (blockIdx.z == 1) ? bk : bv;
    uint16_t*       O = (blockIdx.z == 0) ? Oq : (blockIdx.z == 1) ? Ok : Ov;
    gemm_body(A, W, bb, O, blockIdx.y * 128, blockIdx.x * 128, 1, smg);
}

__global__ __launch_bounds__(256) void gemm_out(
    const uint16_t* __restrict__ A, const uint16_t* __restrict__ W,
    const float* __restrict__ bias, float* __restrict__ C)
{
    extern __shared__ uint8_t smg[];
    gemm_body(A, W, bias, C, blockIdx.y * 128, blockIdx.x * 128, 0, smg);
}

// ---------------- flash attention fp16: Br=128 (8 warps x 16 rows), Bc=64 ----------------
// smem: Q at 0 (128 x 144B = 18432), K at 18432 (2 x 64 x 144 = 18432), V at 36864.
#define QB 0
#define KB 18432
#define VB 36864
#define FLASH_SMEM 55296

__global__ __launch_bounds__(256) void flash_attn(const int* __restrict__ mask)
{
    extern __shared__ uint8_t smf[];
    const uint32_t smb = (uint32_t)__cvta_generic_to_shared(smf);

    const int qt  = blockIdx.x;       // 0..15 (128 rows each)
    const int bh  = blockIdx.y;
    const int b   = bh >> 4;
    const int h   = bh & 15;
    const uint16_t* Qg = g_q + (size_t)bh * Sv * DHv + (size_t)qt * 128 * DHv;
    const uint16_t* Kg = g_k + (size_t)bh * Sv * DHv;
    const uint16_t* Vg = g_v + (size_t)bh * Sv * DHv;
    const int* mrow = mask + b * Sv;

    const int tid  = threadIdx.x;
    const int warp = tid >> 5;
    const int lane = tid & 31;
    const int g    = lane >> 2;
    const int tig  = lane & 3;
    const int rw   = warp * 16;       // warp's 16 q-rows
    const int lrow = lane & 15;
    const int lhalf = (lane >> 4) << 4;   // bytes

    // stage Q (128 x 64 halves -> rows padded to 144B)
    #pragma unroll
    for (int i = tid; i < 1024; i += 256) {
        int r = i >> 3, c = i & 7;
        *(uint4*)(smf + QB + r * 144 + c * 16) = *(const uint4*)&Qg[r * 64 + c * 8];
    }

    auto issue_kv = [&](int st, int jt) {
        #pragma unroll
        for (int u = 0; u < 2; u++) {
            int id = tid + u * 256;
            int r = id >> 3, c = id & 7;
            cpa16(smb + KB + (uint32_t)(st * 9216 + r * 144 + c * 16),
                  &Kg[(jt * 64 + r) * 64 + c * 8]);
        }
        #pragma unroll
        for (int u = 0; u < 2; u++) {
            int id = tid + u * 256;
            int r = id >> 3, c = id & 7;
            cpa16(smb + VB + (uint32_t)(st * 9216 + r * 144 + c * 16),
                  &Vg[(jt * 64 + r) * 64 + c * 8]);
        }
        cpa_commit();
    };

    float m_lo = -1e30f, m_hi = -1e30f, l_lo = 0.f, l_hi = 0.f;
    float o[8][4];
    #pragma unroll
    for (int n = 0; n < 8; n++)
        #pragma unroll
        for (int q = 0; q < 4; q++) o[n][q] = 0.f;

    const float scale2 = 0.0450842298f;   // (1/sqrt(1024)) * log2(e)
    const uint32_t qAddr = smb + QB + (uint32_t)((rw + lrow) * 144) + lhalf;

    issue_kv(0, 0);

    for (int jt = 0; jt < Sv / 64; jt++) {
        asm volatile("cp.async.wait_group 0;" ::: "memory");
        __syncthreads();
        if (jt + 1 < Sv / 64) issue_kv((jt + 1) & 1, jt + 1);

        const uint32_t kAddr = smb + KB + (uint32_t)((jt & 1) * 9216 + lrow * 144) + lhalf;
        const uint32_t vAddr = smb + VB + (uint32_t)((jt & 1) * 9216 + lrow * 144) + lhalf;

        // ---- S = Q @ K^T ----
        float s[8][4];
        #pragma unroll
        for (int n = 0; n < 8; n++)
            #pragma unroll
            for (int q = 0; q < 4; q++) s[n][q] = 0.f;

        #pragma unroll
        for (int kc = 0; kc < 4; kc++) {
            uint32_t aq[4];
            ldsm_x4(aq[0], aq[1], aq[2], aq[3], qAddr + (uint32_t)(kc * 32));
            uint32_t kf[8][2];
            #pragma unroll
            for (int np = 0; np < 4; np++)
                ldsm_x4(kf[2*np][0], kf[2*np+1][0], kf[2*np][1], kf[2*np+1][1],
                        kAddr + (uint32_t)(np * 2304 + kc * 32));
            #pragma unroll
            for (int n = 0; n < 8; n++)
                mma_f16(s[n], aq, kf[n]);
        }

        // ---- mask + scale + rowmax ----
        float rmax_lo = -1e30f, rmax_hi = -1e30f;
        #pragma unroll
        for (int n = 0; n < 8; n++) {
            int c0 = jt * 64 + n * 8 + 2 * tig;
            float msk0 = mrow[c0]     ? 0.f : -1e30f;
            float msk1 = mrow[c0 + 1] ? 0.f : -1e30f;
            s[n][0] = s[n][0] * scale2 + msk0;
            s[n][1] = s[n][1] * scale2 + msk1;
            s[n][2] = s[n][2] * scale2 + msk0;
            s[n][3] = s[n][3] * scale2 + msk1;
            rmax_lo = fmaxf(rmax_lo, fmaxf(s[n][0], s[n][1]));
            rmax_hi = fmaxf(rmax_hi, fmaxf(s[n][2], s[n][3]));
        }
        rmax_lo = fmaxf(rmax_lo, __shfl_xor_sync(0xffffffffu, rmax_lo, 1));
        rmax_lo = fmaxf(rmax_lo, __shfl_xor_sync(0xffffffffu, rmax_lo, 2));
        rmax_hi = fmaxf(rmax_hi, __shfl_xor_sync(0xffffffffu, rmax_hi, 1));
        rmax_hi = fmaxf(rmax_hi, __shfl_xor_sync(0xffffffffu, rmax_hi, 2));

        float mn_lo = fmaxf(m_lo, rmax_lo);
        float mn_hi = fmaxf(m_hi, rmax_hi);
        float al_lo = exp2f(m_lo - mn_lo);
        float al_hi = exp2f(m_hi - mn_hi);
        m_lo = mn_lo; m_hi = mn_hi;

        float rs_lo = 0.f, rs_hi = 0.f;
        #pragma unroll
        for (int n = 0; n < 8; n++) {
            s[n][0] = exp2f(s[n][0] - mn_lo);
            s[n][1] = exp2f(s[n][1] - mn_lo);
            s[n][2] = exp2f(s[n][2] - mn_hi);
            s[n][3] = exp2f(s[n][3] - mn_hi);
            rs_lo += s[n][0] + s[n][1];
            rs_hi += s[n][2] + s[n][3];
        }
        rs_lo += __shfl_xor_sync(0xffffffffu, rs_lo, 1);
        rs_lo += __shfl_xor_sync(0xffffffffu, rs_lo, 2);
        rs_hi += __shfl_xor_sync(0xffffffffu, rs_hi, 1);
        rs_hi += __shfl_xor_sync(0xffffffffu, rs_hi, 2);
        l_lo = l_lo * al_lo + rs_lo;
        l_hi = l_hi * al_hi + rs_hi;

        #pragma unroll
        for (int n = 0; n < 8; n++) {
            o[n][0] *= al_lo; o[n][1] *= al_lo;
            o[n][2] *= al_hi; o[n][3] *= al_hi;
        }

        // ---- O += P @ V : P packed from registers, V via ldmatrix.trans ----
        #pragma unroll
        for (int c = 0; c < 4; c++) {
            uint32_t vf[8][2];
            #pragma unroll
            for (int jp = 0; jp < 4; jp++)
                ldsm_x4t(vf[2*jp][0], vf[2*jp][1], vf[2*jp+1][0], vf[2*jp+1][1],
                         vAddr + (uint32_t)(c * 2304 + jp * 32));
            uint32_t a[4];
            a[0] = pack_f16x2(s[2*c  ][1], s[2*c  ][0]);
            a[1] = pack_f16x2(s[2*c  ][3], s[2*c  ][2]);
            a[2] = pack_f16x2(s[2*c+1][1], s[2*c+1][0]);
            a[3] = pack_f16x2(s[2*c+1][3], s[2*c+1][2]);
            #pragma unroll
            for (int n = 0; n < 8; n++)
                mma_f16(o[n], a, vf[n]);
        }
    }

    float il_lo = 1.f / l_lo;
    float il_hi = 1.f / l_hi;
    int s0 = qt * 128 + rw + g;
    int s1 = s0 + 8;
    size_t base0 = (((size_t)b * Sv + s0) * Hv + h) * DHv;
    size_t base1 = (((size_t)b * Sv + s1) * Hv + h) * DHv;
    #pragma unroll
    for (int n = 0; n < 8; n++) {
        int dh = n * 8 + 2 * tig;
        *(uint32_t*)&g_ctx[base0 + dh] = pack_f16x2(o[n][1] * il_lo, o[n][0] * il_lo);
        *(uint32_t*)&g_ctx[base1 + dh] = pack_f16x2(o[n][3] * il_hi, o[n][2] * il_hi);
    }
}

extern "C" void kernel_launch(void* const* d_in, const int* in_sizes, int n_in,
                              void* d_out, int out_size)
{
    const float* query = (const float*)d_in[0];
    const float* key   = (const float*)d_in[1];
    const float* value = (const float*)d_in[2];
    const int*   mask  = (const int*)  d_in[3];
    const float* Wq    = (const float*)d_in[4];
    const float* bq    = (const float*)d_in[5];
    const float* Wk    = (const float*)d_in[6];
    const float* bk    = (const float*)d_in[7];
    const float* Wv    = (const float*)d_in[8];
    const float* bv    = (const float*)d_in[9];
    const float* Wo    = (const float*)d_in[10];
    const float* bo    = (const float*)d_in[11];
    float* out = (float*)d_out;

    uint16_t *qin, *kin, *vin, *wq, *wk, *wv, *wo, *gq, *gk, *gv, *gctx;
    cudaGetSymbolAddress((void**)&qin,  g_qin);
    cudaGetSymbolAddress((void**)&kin,  g_kin);
    cudaGetSymbolAddress((void**)&vin,  g_vin);
    cudaGetSymbolAddress((void**)&wq,   g_wq);
    cudaGetSymbolAddress((void**)&wk,   g_wk);
    cudaGetSymbolAddress((void**)&wv,   g_wv);
    cudaGetSymbolAddress((void**)&wo,   g_wo);
    cudaGetSymbolAddress((void**)&gq,   g_q);
    cudaGetSymbolAddress((void**)&gk,   g_k);
    cudaGetSymbolAddress((void**)&gv,   g_v);
    cudaGetSymbolAddress((void**)&gctx, g_ctx);

    const int smem_gemm = 61440;
    const int smem_attn = FLASH_SMEM;    // 55296
    cudaFuncSetAttribute(proj_qkv,   cudaFuncAttributeMaxDynamicSharedMemorySize, smem_gemm);
    cudaFuncSetAttribute(gemm_out,   cudaFuncAttributeMaxDynamicSharedMemorySize, smem_gemm);
    cudaFuncSetAttribute(flash_attn, cudaFuncAttributeMaxDynamicSharedMemorySize, smem_attn);

    const int NIN4 = Mv * Dv / 4;
    const int NW4  = Dv * Dv / 4;
    cvt3_kernel<<<dim3(1024, 3), 256>>>((const float4*)query, (const float4*)key, (const float4*)value,
                                        (uint2*)qin, (uint2*)kin, (uint2*)vin, NIN4);
    cvt4_kernel<<<dim3(256, 4), 256>>>((const float4*)Wq, (const float4*)Wk, (const float4*)Wv, (const float4*)Wo,
                                       (uint2*)wq, (uint2*)wk, (uint2*)wv, (uint2*)wo, NW4);

    proj_qkv<<<dim3(Dv / 128, Mv / 128, 3), 256, smem_gemm>>>(
        qin, kin, vin, wq, wk, wv, bq, bk, bv, gq, gk, gv);

    flash_attn<<<dim3(Sv / 128, Bv * Hv), 256, smem_attn>>>(mask);

    gemm_out<<<dim3(Dv / 128, Mv / 128), 256, smem_gemm>>>(gctx, wo, bo, out);
}

// round 17
// speedup vs baseline: 1.9847x; 1.0666x over previous
#include <cuda_runtime.h>
#include <cstdint>

#define Bv 4
#define Sv 2048
#define Dv 1024
#define Hv 16
#define DHv 64
#define Mv (Bv*Sv)          // 8192

// Scratch: fp16 everywhere
__device__ uint16_t g_qin[Mv*Dv];
__device__ uint16_t g_kin[Mv*Dv];
__device__ uint16_t g_vin[Mv*Dv];
__device__ uint16_t g_wq[Dv*Dv];
__device__ uint16_t g_wk[Dv*Dv];
__device__ uint16_t g_wv[Dv*Dv];
__device__ uint16_t g_wo[Dv*Dv];
__device__ uint16_t g_q[Mv*Dv];    // [b,h,s,dh]
__device__ uint16_t g_k[Mv*Dv];
__device__ uint16_t g_v[Mv*Dv];
__device__ uint16_t g_ctx[Mv*Dv];  // [b,s,h,dh]

__device__ __forceinline__ uint32_t pack_f16x2(float hi, float lo) {
    uint32_t r;
    asm("cvt.rn.f16x2.f32 %0, %1, %2;" : "=r"(r) : "f"(hi), "f"(lo));
    return r;
}

__device__ __forceinline__ void mma_f16(float c[4], const uint32_t a[4], const uint32_t b[2]) {
    asm volatile(
        "mma.sync.aligned.m16n8k16.row.col.f32.f16.f16.f32 "
        "{%0,%1,%2,%3}, {%4,%5,%6,%7}, {%8,%9}, {%0,%1,%2,%3};\n"
        : "+f"(c[0]), "+f"(c[1]), "+f"(c[2]), "+f"(c[3])
        : "r"(a[0]), "r"(a[1]), "r"(a[2]), "r"(a[3]), "r"(b[0]), "r"(b[1]));
}

__device__ __forceinline__ void ldsm_x4(uint32_t& r0, uint32_t& r1, uint32_t& r2, uint32_t& r3,
                                        uint32_t addr) {
    asm volatile("ldmatrix.sync.aligned.m8n8.x4.shared.b16 {%0,%1,%2,%3}, [%4];"
        : "=r"(r0), "=r"(r1), "=r"(r2), "=r"(r3) : "r"(addr));
}
__device__ __forceinline__ void ldsm_x4t(uint32_t& r0, uint32_t& r1, uint32_t& r2, uint32_t& r3,
                                         uint32_t addr) {
    asm volatile("ldmatrix.sync.aligned.m8n8.x4.trans.shared.b16 {%0,%1,%2,%3}, [%4];"
        : "=r"(r0), "=r"(r1), "=r"(r2), "=r"(r3) : "r"(addr));
}

__device__ __forceinline__ void cpa16(uint32_t saddr, const void* gptr) {
    asm volatile("cp.async.cg.shared.global [%0], [%1], 16;" :: "r"(saddr), "l"(gptr));
}
__device__ __forceinline__ void cpa_commit() {
    asm volatile("cp.async.commit_group;" ::: "memory");
}

// ---------------- conversions: fp32 -> fp16 ----------------

__global__ __launch_bounds__(256) void cvt3_kernel(
    const float4* __restrict__ a, const float4* __restrict__ b, const float4* __restrict__ c,
    uint2* __restrict__ oa, uint2* __restrict__ ob, uint2* __restrict__ oc, int n4)
{
    const float4* in  = (blockIdx.y == 0) ? a  : (blockIdx.y == 1) ? b  : c;
    uint2*        out = (blockIdx.y == 0) ? oa : (blockIdx.y == 1) ? ob : oc;
    int i = blockIdx.x * blockDim.x + threadIdx.x;
    int stride = gridDim.x * blockDim.x;
    for (; i < n4; i += stride) {
        float4 v = in[i];
        out[i] = make_uint2(pack_f16x2(v.y, v.x), pack_f16x2(v.w, v.z));
    }
}

__global__ __launch_bounds__(256) void cvt4_kernel(
    const float4* __restrict__ a, const float4* __restrict__ b,
    const float4* __restrict__ c, const float4* __restrict__ d,
    uint2* __restrict__ oa, uint2* __restrict__ ob,
    uint2* __restrict__ oc, uint2* __restrict__ od, int n4)
{
    const float4* in  = (blockIdx.y == 0) ? a  : (blockIdx.y == 1) ? b  : (blockIdx.y == 2) ? c  : d;
    uint2*        out = (blockIdx.y == 0) ? oa : (blockIdx.y == 1) ? ob : (blockIdx.y == 2) ? oc : od;
    int i = blockIdx.x * blockDim.x + threadIdx.x;
    int stride = gridDim.x * blockDim.x;
    for (; i < n4; i += stride) {
        float4 v = in[i];
        out[i] = make_uint2(pack_f16x2(v.y, v.x), pack_f16x2(v.w, v.z));
    }
}

// ---------------- GEMM fp16: 128x128 tile, warp 64x32, k-slab 64, 3-stage cp.async ----------------
// Stage: A[128 rows][64 halves, row stride 144B] + B same -> 2*18432 = 36864B/stage.
// 3 stages = 110592B, 2 CTAs/SM.

#define GSTG 36864

__device__ __forceinline__ void gemm_body(
    const uint16_t* __restrict__ A, const uint16_t* __restrict__ W,
    const float* __restrict__ bias, void* __restrict__ Cout,
    int bm, int bn, int scatter, uint8_t* smg)
{
    const uint32_t smb = (uint32_t)__cvta_generic_to_shared(smg);

    const int tid  = threadIdx.x;
    const int warp = tid >> 5;
    const int lane = tid & 31;
    const int wm   = (warp >> 2) * 64;
    const int wn   = (warp & 3) * 32;
    const int g    = lane >> 2;
    const int tig  = lane & 3;
    const int lrow = lane & 15;
    const int lhalf = (lane >> 4) << 4;   // bytes

    float acc[4][4][4];
    #pragma unroll
    for (int i = 0; i < 4; i++)
        #pragma unroll
        for (int j = 0; j < 4; j++)
            #pragma unroll
            for (int t = 0; t < 4; t++) acc[i][j][t] = 0.f;

    auto issue = [&](int st, int kt) {
        uint32_t base = smb + (uint32_t)st * GSTG;
        #pragma unroll
        for (int u = 0; u < 4; u++) {
            int id = tid + u * 256;          // 0..1023
            int r = id >> 3, c = id & 7;
            cpa16(base + (uint32_t)(r * 144 + c * 16),
                  &A[(size_t)(bm + r) * Dv + kt + c * 8]);
        }
        #pragma unroll
        for (int u = 0; u < 4; u++) {
            int id = tid + u * 256;
            int r = id >> 3, c = id & 7;
            cpa16(base + 18432u + (uint32_t)(r * 144 + c * 16),
                  &W[(size_t)(bn + r) * Dv + kt + c * 8]);
        }
        cpa_commit();
    };

    issue(0, 0);
    issue(1, 64);

    for (int t = 0; t < 16; t++) {
        if (t == 15) asm volatile("cp.async.wait_group 0;" ::: "memory");
        else         asm volatile("cp.async.wait_group 1;" ::: "memory");
        __syncthreads();
        if (t + 2 < 16) issue((t + 2) % 3, (t + 2) * 64);

        const uint32_t stBase = smb + (uint32_t)((t % 3) * GSTG);
        const uint32_t aAddr = stBase + (uint32_t)((wm + lrow) * 144) + lhalf;
        const uint32_t bAddr = stBase + 18432u + (uint32_t)((wn + lrow) * 144) + lhalf;

        #pragma unroll
        for (int kc = 0; kc < 4; kc++) {
            uint32_t af[4][4], bf[4][2];
            #pragma unroll
            for (int i = 0; i < 4; i++)
                ldsm_x4(af[i][0], af[i][1], af[i][2], af[i][3],
                        aAddr + (uint32_t)(i * 2304 + kc * 32));
            #pragma unroll
            for (int jp = 0; jp < 2; jp++)
                ldsm_x4(bf[2*jp][0], bf[2*jp+1][0], bf[2*jp][1], bf[2*jp+1][1],
                        bAddr + (uint32_t)(jp * 2304 + kc * 32));
            #pragma unroll
            for (int i = 0; i < 4; i++)
                #pragma unroll
                for (int j = 0; j < 4; j++)
                    mma_f16(acc[i][j], af[i], bf[j]);
        }
        __syncthreads();
    }

    #pragma unroll
    for (int i = 0; i < 4; i++) {
        #pragma unroll
        for (int j = 0; j < 4; j++) {
            int r0 = bm + wm + i * 16 + g;
            int r1 = r0 + 8;
            int c0 = bn + wn + j * 8 + 2 * tig;
            float b0 = bias[c0], b1 = bias[c0 + 1];
            float v00 = acc[i][j][0] + b0, v01 = acc[i][j][1] + b1;
            float v10 = acc[i][j][2] + b0, v11 = acc[i][j][3] + b1;
            if (scatter) {
                uint16_t* C = (uint16_t*)Cout;
                int b_0 = r0 >> 11, s_0 = r0 & 2047;
                int b_1 = r1 >> 11, s_1 = r1 & 2047;
                int h = c0 >> 6, dh = c0 & 63;
                size_t i0 = ((((size_t)b_0 * Hv + h) * Sv) + s_0) * DHv + dh;
                size_t i1 = ((((size_t)b_1 * Hv + h) * Sv) + s_1) * DHv + dh;
                *(uint32_t*)&C[i0] = pack_f16x2(v01, v00);
                *(uint32_t*)&C[i1] = pack_f16x2(v11, v10);
            } else {
                float* C = (float*)Cout;
                C[(size_t)r0 * Dv + c0] = v00; C[(size_t)r0 * Dv + c0 + 1] = v01;
                C[(size_t)r1 * Dv + c0] = v10; C[(size_t)r1 * Dv + c0 + 1] = v11;
            }
        }
    }
}

__global__ __launch_bounds__(256) void proj_qkv(
    const uint16_t* __restrict__ Aq, const uint16_t* __restrict__ Ak, const uint16_t* __restrict__ Av,
    const uint16_t* __restrict__ Wq, const uint16_t* __restrict__ Wk, const uint16_t* __restrict__ Wv,
    const float* __restrict__ bq, const float* __restrict__ bk, const float* __restrict__ bv,
    uint16_t* __restrict__ Oq, uint16_t* __restrict__ Ok, uint16_t* __restrict__ Ov)
{
    extern __shared__ uint8_t smg[];
    const uint16_t* A = (blockIdx.z == 0) ? Aq : (blockIdx.z == 1) ? Ak : Av;
    const uint16_t* W = (blockIdx.z == 0) ? Wq : (blockIdx.z == 1) ? Wk : Wv;
    const float*    bb = (blockIdx.z == 0) ? bq : (blockIdx.z == 1) ? bk : bv;
    uint16_t*       O = (blockIdx.z == 0) ? Oq : (blockIdx.z == 1) ? Ok : Ov;
    gemm_body(A, W, bb, O, blockIdx.y * 128, blockIdx.x * 128, 1, smg);
}

__global__ __launch_bounds__(256) void gemm_out(
    const uint16_t* __restrict__ A, const uint16_t* __restrict__ W,
    const float* __restrict__ bias, float* __restrict__ C)
{
    extern __shared__ uint8_t smg[];
    gemm_body(A, W, bias, C, blockIdx.y * 128, blockIdx.x * 128, 0, smg);
}

// ---------------- flash attention fp16: Br=128 (8 warps x 16 rows), Bc=64 ----------------
// smem: Q at 0 (128 x 144B = 18432), K at 18432 (2 x 64 x 144 = 18432), V at 36864.
#define QB 0
#define KB 18432
#define VB 36864
#define FLASH_SMEM 55296

__global__ __launch_bounds__(256) void flash_attn(const int* __restrict__ mask)
{
    extern __shared__ uint8_t smf[];
    const uint32_t smb = (uint32_t)__cvta_generic_to_shared(smf);

    const int qt  = blockIdx.x;       // 0..15 (128 rows each)
    const int bh  = blockIdx.y;
    const int b   = bh >> 4;
    const int h   = bh & 15;
    const uint16_t* Qg = g_q + (size_t)bh * Sv * DHv + (size_t)qt * 128 * DHv;
    const uint16_t* Kg = g_k + (size_t)bh * Sv * DHv;
    const uint16_t* Vg = g_v + (size_t)bh * Sv * DHv;
    const int* mrow = mask + b * Sv;

    const int tid  = threadIdx.x;
    const int warp = tid >> 5;
    const int lane = tid & 31;
    const int g    = lane >> 2;
    const int tig  = lane & 3;
    const int rw   = warp * 16;       // warp's 16 q-rows
    const int lrow = lane & 15;
    const int lhalf = (lane >> 4) << 4;   // bytes

    // stage Q (128 x 64 halves -> rows padded to 144B)
    #pragma unroll
    for (int i = tid; i < 1024; i += 256) {
        int r = i >> 3, c = i & 7;
        *(uint4*)(smf + QB + r * 144 + c * 16) = *(const uint4*)&Qg[r * 64 + c * 8];
    }

    auto issue_kv = [&](int st, int jt) {
        #pragma unroll
        for (int u = 0; u < 2; u++) {
            int id = tid + u * 256;
            int r = id >> 3, c = id & 7;
            cpa16(smb + KB + (uint32_t)(st * 9216 + r * 144 + c * 16),
                  &Kg[(jt * 64 + r) * 64 + c * 8]);
        }
        #pragma unroll
        for (int u = 0; u < 2; u++) {
            int id = tid + u * 256;
            int r = id >> 3, c = id & 7;
            cpa16(smb + VB + (uint32_t)(st * 9216 + r * 144 + c * 16),
                  &Vg[(jt * 64 + r) * 64 + c * 8]);
        }
        cpa_commit();
    };

    float m_lo = -1e30f, m_hi = -1e30f, l_lo = 0.f, l_hi = 0.f;
    float o[8][4];
    #pragma unroll
    for (int n = 0; n < 8; n++)
        #pragma unroll
        for (int q = 0; q < 4; q++) o[n][q] = 0.f;

    const float scale2 = 0.0450842298f;   // (1/sqrt(1024)) * log2(e)
    const uint32_t qAddr = smb + QB + (uint32_t)((rw + lrow) * 144) + lhalf;

    issue_kv(0, 0);

    for (int jt = 0; jt < Sv / 64; jt++) {
        asm volatile("cp.async.wait_group 0;" ::: "memory");
        __syncthreads();
        if (jt + 1 < Sv / 64) issue_kv((jt + 1) & 1, jt + 1);

        const uint32_t kAddr = smb + KB + (uint32_t)((jt & 1) * 9216 + lrow * 144) + lhalf;
        const uint32_t vAddr = smb + VB + (uint32_t)((jt & 1) * 9216 + lrow * 144) + lhalf;

        // ---- S = Q @ K^T ----
        float s[8][4];
        #pragma unroll
        for (int n = 0; n < 8; n++)
            #pragma unroll
            for (int q = 0; q < 4; q++) s[n][q] = 0.f;

        #pragma unroll
        for (int kc = 0; kc < 4; kc++) {
            uint32_t aq[4];
            ldsm_x4(aq[0], aq[1], aq[2], aq[3], qAddr + (uint32_t)(kc * 32));
            uint32_t kf[8][2];
            #pragma unroll
            for (int np = 0; np < 4; np++)
                ldsm_x4(kf[2*np][0], kf[2*np+1][0], kf[2*np][1], kf[2*np+1][1],
                        kAddr + (uint32_t)(np * 2304 + kc * 32));
            #pragma unroll
            for (int n = 0; n < 8; n++)
                mma_f16(s[n], aq, kf[n]);
        }

        // ---- mask + scale + rowmax ----
        float rmax_lo = -1e30f, rmax_hi = -1e30f;
        #pragma unroll
        for (int n = 0; n < 8; n++) {
            int c0 = jt * 64 + n * 8 + 2 * tig;
            float msk0 = mrow[c0]     ? 0.f : -1e30f;
            float msk1 = mrow[c0 + 1] ? 0.f : -1e30f;
            s[n][0] = s[n][0] * scale2 + msk0;
            s[n][1] = s[n][1] * scale2 + msk1;
            s[n][2] = s[n][2] * scale2 + msk0;
            s[n][3] = s[n][3] * scale2 + msk1;
            rmax_lo = fmaxf(rmax_lo, fmaxf(s[n][0], s[n][1]));
            rmax_hi = fmaxf(rmax_hi, fmaxf(s[n][2], s[n][3]));
        }
        rmax_lo = fmaxf(rmax_lo, __shfl_xor_sync(0xffffffffu, rmax_lo, 1));
        rmax_lo = fmaxf(rmax_lo, __shfl_xor_sync(0xffffffffu, rmax_lo, 2));
        rmax_hi = fmaxf(rmax_hi, __shfl_xor_sync(0xffffffffu, rmax_hi, 1));
        rmax_hi = fmaxf(rmax_hi, __shfl_xor_sync(0xffffffffu, rmax_hi, 2));

        float mn_lo = fmaxf(m_lo, rmax_lo);
        float mn_hi = fmaxf(m_hi, rmax_hi);
        float al_lo = exp2f(m_lo - mn_lo);
        float al_hi = exp2f(m_hi - mn_hi);
        m_lo = mn_lo; m_hi = mn_hi;

        float rs_lo = 0.f, rs_hi = 0.f;
        #pragma unroll
        for (int n = 0; n < 8; n++) {
            s[n][0] = exp2f(s[n][0] - mn_lo);
            s[n][1] = exp2f(s[n][1] - mn_lo);
            s[n][2] = exp2f(s[n][2] - mn_hi);
            s[n][3] = exp2f(s[n][3] - mn_hi);
            rs_lo += s[n][0] + s[n][1];
            rs_hi += s[n][2] + s[n][3];
        }
        rs_lo += __shfl_xor_sync(0xffffffffu, rs_lo, 1);
        rs_lo += __shfl_xor_sync(0xffffffffu, rs_lo, 2);
        rs_hi += __shfl_xor_sync(0xffffffffu, rs_hi, 1);
        rs_hi += __shfl_xor_sync(0xffffffffu, rs_hi, 2);
        l_lo = l_lo * al_lo + rs_lo;
        l_hi = l_hi * al_hi + rs_hi;

        // O-rescale only when max actually moved (al != 1 somewhere in warp)
        if (__any_sync(0xffffffffu, (al_lo != 1.f) | (al_hi != 1.f))) {
            #pragma unroll
            for (int n = 0; n < 8; n++) {
                o[n][0] *= al_lo; o[n][1] *= al_lo;
                o[n][2] *= al_hi; o[n][3] *= al_hi;
            }
        }

        // ---- O += P @ V : P packed from registers, V via ldmatrix.trans ----
        #pragma unroll
        for (int c = 0; c < 4; c++) {
            uint32_t vf[8][2];
            #pragma unroll
            for (int jp = 0; jp < 4; jp++)
                ldsm_x4t(vf[2*jp][0], vf[2*jp][1], vf[2*jp+1][0], vf[2*jp+1][1],
                         vAddr + (uint32_t)(c * 2304 + jp * 32));
            uint32_t a[4];
            a[0] = pack_f16x2(s[2*c  ][1], s[2*c  ][0]);
            a[1] = pack_f16x2(s[2*c  ][3], s[2*c  ][2]);
            a[2] = pack_f16x2(s[2*c+1][1], s[2*c+1][0]);
            a[3] = pack_f16x2(s[2*c+1][3], s[2*c+1][2]);
            #pragma unroll
            for (int n = 0; n < 8; n++)
                mma_f16(o[n], a, vf[n]);
        }
    }

    float il_lo = 1.f / l_lo;
    float il_hi = 1.f / l_hi;
    int s0 = qt * 128 + rw + g;
    int s1 = s0 + 8;
    size_t base0 = (((size_t)b * Sv + s0) * Hv + h) * DHv;
    size_t base1 = (((size_t)b * Sv + s1) * Hv + h) * DHv;
    #pragma unroll
    for (int n = 0; n < 8; n++) {
        int dh = n * 8 + 2 * tig;
        *(uint32_t*)&g_ctx[base0 + dh] = pack_f16x2(o[n][1] * il_lo, o[n][0] * il_lo);
        *(uint32_t*)&g_ctx[base1 + dh] = pack_f16x2(o[n][3] * il_hi, o[n][2] * il_hi);
    }
}

extern "C" void kernel_launch(void* const* d_in, const int* in_sizes, int n_in,
                              void* d_out, int out_size)
{
    const float* query = (const float*)d_in[0];
    const float* key   = (const float*)d_in[1];
    const float* value = (const float*)d_in[2];
    const int*   mask  = (const int*)  d_in[3];
    const float* Wq    = (const float*)d_in[4];
    const float* bq    = (const float*)d_in[5];
    const float* Wk    = (const float*)d_in[6];
    const float* bk    = (const float*)d_in[7];
    const float* Wv    = (const float*)d_in[8];
    const float* bv    = (const float*)d_in[9];
    const float* Wo    = (const float*)d_in[10];
    const float* bo    = (const float*)d_in[11];
    float* out = (float*)d_out;

    uint16_t *qin, *kin, *vin, *wq, *wk, *wv, *wo, *gq, *gk, *gv, *gctx;
    cudaGetSymbolAddress((void**)&qin,  g_qin);
    cudaGetSymbolAddress((void**)&kin,  g_kin);
    cudaGetSymbolAddress((void**)&vin,  g_vin);
    cudaGetSymbolAddress((void**)&wq,   g_wq);
    cudaGetSymbolAddress((void**)&wk,   g_wk);
    cudaGetSymbolAddress((void**)&wv,   g_wv);
    cudaGetSymbolAddress((void**)&wo,   g_wo);
    cudaGetSymbolAddress((void**)&gq,   g_q);
    cudaGetSymbolAddress((void**)&gk,   g_k);
    cudaGetSymbolAddress((void**)&gv,   g_v);
    cudaGetSymbolAddress((void**)&gctx, g_ctx);

    const int smem_gemm = 3 * GSTG;      // 110592
    const int smem_attn = FLASH_SMEM;    // 55296
    cudaFuncSetAttribute(proj_qkv,   cudaFuncAttributeMaxDynamicSharedMemorySize, smem_gemm);
    cudaFuncSetAttribute(gemm_out,   cudaFuncAttributeMaxDynamicSharedMemorySize, smem_gemm);
    cudaFuncSetAttribute(flash_attn, cudaFuncAttributeMaxDynamicSharedMemorySize, smem_attn);

    const int NIN4 = Mv * Dv / 4;
    const int NW4  = Dv * Dv / 4;
    cvt3_kernel<<<dim3(1024, 3), 256>>>((const float4*)query, (const float4*)key, (const float4*)value,
                                        (uint2*)qin, (uint2*)kin, (uint2*)vin, NIN4);
    cvt4_kernel<<<dim3(256, 4), 256>>>((const float4*)Wq, (const float4*)Wk, (const float4*)Wv, (const float4*)Wo,
                                       (uint2*)wq, (uint2*)wk, (uint2*)wv, (uint2*)wo, NW4);

    proj_qkv<<<dim3(Dv / 128, Mv / 128, 3), 256, smem_gemm>>>(
        qin, kin, vin, wq, wk, wv, bq, bk, bv, gq, gk, gv);

    flash_attn<<<dim3(Sv / 128, Bv * Hv), 256, smem_attn>>>(mask);

    gemm_out<<<dim3(Dv / 128, Mv / 128), 256, smem_gemm>>>(gctx, wo, bo, out);
}